// round 1
// baseline (speedup 1.0000x reference)
#include <cuda_runtime.h>

// Problem constants
namespace {
constexpr int B_      = 2;
constexpr int N_      = 2048;
constexpr int DIM_    = 1024;
constexpr int HEADS_  = 8;
constexpr int DHEAD_  = 64;
constexpr int INNER_  = 512;   // HEADS*DHEAD
constexpr float EPS_  = 1e-5f;
constexpr int NCHUNK_ = 16;
constexpr int CH_     = N_ / NCHUNK_;  // 128
}

// Scratch (static device allocations; runtime alloc is forbidden)
__device__ float g_xn [B_ * N_ * DIM_];                       // 16 MB
__device__ float g_q  [B_ * N_ * INNER_];                     //  8 MB
__device__ float g_kv [B_ * N_ * 2 * INNER_];                 // 16 MB
__device__ float g_sim[(size_t)B_ * HEADS_ * N_ * N_];        // 256 MB
__device__ float g_att[B_ * N_ * INNER_];                     //  8 MB
__device__ float g_ps [B_ * NCHUNK_ * DIM_];
__device__ float g_pss[B_ * NCHUNK_ * DIM_];
__device__ float g_scale[B_ * DIM_];
__device__ float g_bias [B_ * DIM_];

// ---------------------------------------------------------------------------
// LayerNorm over sequence axis (axis=1): stats per (b, d) column.
// Pass 1: partial sums over n-chunks (coalesced along d).
// ---------------------------------------------------------------------------
__global__ void ln_partial_kernel(const float* __restrict__ x) {
    int d = blockIdx.x * blockDim.x + threadIdx.x;
    int c = blockIdx.y;
    int b = blockIdx.z;
    const float* px = x + ((size_t)b * N_ + (size_t)c * CH_) * DIM_ + d;
    float s = 0.f, ss = 0.f;
#pragma unroll 4
    for (int n = 0; n < CH_; n++) {
        float v = px[(size_t)n * DIM_];
        s += v;
        ss += v * v;
    }
    size_t o = ((size_t)b * NCHUNK_ + c) * DIM_ + d;
    g_ps[o]  = s;
    g_pss[o] = ss;
}

// Pass 2: finalize mean/var, fold gain into scale/bias.
__global__ void ln_stats_kernel(const float* __restrict__ g) {
    int d = blockIdx.x * blockDim.x + threadIdx.x;
    int b = blockIdx.z;
    float s = 0.f, ss = 0.f;
#pragma unroll
    for (int c = 0; c < NCHUNK_; c++) {
        size_t o = ((size_t)b * NCHUNK_ + c) * DIM_ + d;
        s += g_ps[o];
        ss += g_pss[o];
    }
    float mean = s * (1.f / N_);
    float var  = fmaf(-mean, mean, ss * (1.f / N_));
    float sc   = rsqrtf(var + EPS_) * g[d];
    g_scale[b * DIM_ + d] = sc;
    g_bias[b * DIM_ + d]  = -mean * sc;
}

// Pass 3: normalize (vectorized).
__global__ void ln_norm_kernel(const float* __restrict__ x) {
    int i = blockIdx.x * blockDim.x + threadIdx.x;  // float4 index
    int elem = i * 4;
    int d = elem & (DIM_ - 1);
    int b = elem / (N_ * DIM_);
    float4 xv = reinterpret_cast<const float4*>(x)[i];
    float4 sc = *reinterpret_cast<const float4*>(&g_scale[b * DIM_ + d]);
    float4 bi = *reinterpret_cast<const float4*>(&g_bias[b * DIM_ + d]);
    float4 r;
    r.x = fmaf(xv.x, sc.x, bi.x);
    r.y = fmaf(xv.y, sc.y, bi.y);
    r.z = fmaf(xv.z, sc.z, bi.z);
    r.w = fmaf(xv.w, sc.w, bi.w);
    reinterpret_cast<float4*>(g_xn)[i] = r;
}

// ---------------------------------------------------------------------------
// Generic batched SGEMM.
//   C[z][i][j] = alpha * sum_k A[z][i][k] * (TB ? B[z][j][k] : B[z][k][j])
// Batch index z decomposed as (z>>3, z&7) applied to (outer, inner) strides.
// All dimensions must be multiples of the tile sizes (no bounds checks).
// ---------------------------------------------------------------------------
template <int BM, int BN, int BK, int TM, int TN, bool TB>
__global__ void __launch_bounds__((BM / TM) * (BN / TN))
sgemm_kernel(const float* __restrict__ A, const float* __restrict__ B,
             float* __restrict__ C,
             int K, int lda, int ldb, int ldc,
             long sAo, long sAi, long sBo, long sBi, long sCo, long sCi,
             float alpha) {
    constexpr int THREADS = (BM / TM) * (BN / TN);
    __shared__ float As[BK][BM];
    __shared__ float Bs[BK][BN];

    const int tid  = threadIdx.x;
    const int bz   = blockIdx.z;
    const int brow = blockIdx.y * BM;
    const int bcol = blockIdx.x * BN;

    const long zo = (long)(bz >> 3);
    const long zi = (long)(bz & 7);
    A += zo * sAo + zi * sAi + (long)brow * lda;
    if (TB) B += zo * sBo + zi * sBi + (long)bcol * ldb;
    else    B += zo * sBo + zi * sBi + bcol;
    C += zo * sCo + zi * sCi;

    const int tx = tid % (BN / TN);
    const int ty = tid / (BN / TN);

    float acc[TM][TN];
#pragma unroll
    for (int i = 0; i < TM; i++)
#pragma unroll
        for (int j = 0; j < TN; j++) acc[i][j] = 0.f;

    for (int kt = 0; kt < K; kt += BK) {
        // Load A tile (BM x BK), store transposed into As[k][row]
        for (int i = tid; i < BM * BK / 4; i += THREADS) {
            int r  = i / (BK / 4);
            int kq = (i % (BK / 4)) * 4;
            float4 v = *reinterpret_cast<const float4*>(A + (long)r * lda + kt + kq);
            As[kq + 0][r] = v.x;
            As[kq + 1][r] = v.y;
            As[kq + 2][r] = v.z;
            As[kq + 3][r] = v.w;
        }
        if (TB) {
            // B is [N, K] row-major -> Bs[k][col]
            for (int i = tid; i < BN * BK / 4; i += THREADS) {
                int c  = i / (BK / 4);
                int kq = (i % (BK / 4)) * 4;
                float4 v = *reinterpret_cast<const float4*>(B + (long)c * ldb + kt + kq);
                Bs[kq + 0][c] = v.x;
                Bs[kq + 1][c] = v.y;
                Bs[kq + 2][c] = v.z;
                Bs[kq + 3][c] = v.w;
            }
        } else {
            // B is [K, N] row-major -> direct copy rows
            for (int i = tid; i < BK * BN / 4; i += THREADS) {
                int k = i / (BN / 4);
                int c = (i % (BN / 4)) * 4;
                *reinterpret_cast<float4*>(&Bs[k][c]) =
                    *reinterpret_cast<const float4*>(B + (long)(kt + k) * ldb + c);
            }
        }
        __syncthreads();

#pragma unroll
        for (int k = 0; k < BK; k++) {
            float a[TM], b[TN];
            *reinterpret_cast<float4*>(&a[0]) =
                *reinterpret_cast<const float4*>(&As[k][ty * 4]);
            *reinterpret_cast<float4*>(&a[4]) =
                *reinterpret_cast<const float4*>(&As[k][BM / 2 + ty * 4]);
            *reinterpret_cast<float4*>(&b[0]) =
                *reinterpret_cast<const float4*>(&Bs[k][tx * 4]);
            *reinterpret_cast<float4*>(&b[4]) =
                *reinterpret_cast<const float4*>(&Bs[k][BN / 2 + tx * 4]);
#pragma unroll
            for (int i = 0; i < TM; i++)
#pragma unroll
                for (int j = 0; j < TN; j++)
                    acc[i][j] = fmaf(a[i], b[j], acc[i][j]);
        }
        __syncthreads();
    }

    // Epilogue: 2x2 quadrants of 4x4 float4 stores
#pragma unroll
    for (int gi = 0; gi < 2; gi++) {
#pragma unroll
        for (int ii = 0; ii < 4; ii++) {
            int r = brow + gi * (BM / 2) + ty * 4 + ii;
#pragma unroll
            for (int gj = 0; gj < 2; gj++) {
                int c = bcol + gj * (BN / 2) + tx * 4;
                float4 o;
                o.x = acc[gi * 4 + ii][gj * 4 + 0] * alpha;
                o.y = acc[gi * 4 + ii][gj * 4 + 1] * alpha;
                o.z = acc[gi * 4 + ii][gj * 4 + 2] * alpha;
                o.w = acc[gi * 4 + ii][gj * 4 + 3] * alpha;
                *reinterpret_cast<float4*>(C + (long)r * ldc + c) = o;
            }
        }
    }
}

// ---------------------------------------------------------------------------
// Row softmax over last axis. One 256-thread block per row of 2048; row held
// entirely in registers (8 floats/thread): one read, one write.
// ---------------------------------------------------------------------------
__global__ void softmax_kernel(float* __restrict__ S) {
    const int tid = threadIdx.x;
    float* p = S + (size_t)blockIdx.x * N_;
    float4 v0 = reinterpret_cast<float4*>(p)[tid];
    float4 v1 = reinterpret_cast<float4*>(p)[256 + tid];

    __shared__ float red[8];

    float m = fmaxf(fmaxf(fmaxf(v0.x, v0.y), fmaxf(v0.z, v0.w)),
                    fmaxf(fmaxf(v1.x, v1.y), fmaxf(v1.z, v1.w)));
#pragma unroll
    for (int o = 16; o; o >>= 1) m = fmaxf(m, __shfl_xor_sync(0xffffffffu, m, o));
    if ((tid & 31) == 0) red[tid >> 5] = m;
    __syncthreads();
    m = red[0];
#pragma unroll
    for (int i = 1; i < 8; i++) m = fmaxf(m, red[i]);
    __syncthreads();  // protect red[] before reuse

    v0.x = __expf(v0.x - m); v0.y = __expf(v0.y - m);
    v0.z = __expf(v0.z - m); v0.w = __expf(v0.w - m);
    v1.x = __expf(v1.x - m); v1.y = __expf(v1.y - m);
    v1.z = __expf(v1.z - m); v1.w = __expf(v1.w - m);

    float s = v0.x + v0.y + v0.z + v0.w + v1.x + v1.y + v1.z + v1.w;
#pragma unroll
    for (int o = 16; o; o >>= 1) s += __shfl_xor_sync(0xffffffffu, s, o);
    if ((tid & 31) == 0) red[tid >> 5] = s;
    __syncthreads();
    s = red[0];
#pragma unroll
    for (int i = 1; i < 8; i++) s += red[i];

    float inv = 1.0f / s;
    v0.x *= inv; v0.y *= inv; v0.z *= inv; v0.w *= inv;
    v1.x *= inv; v1.y *= inv; v1.z *= inv; v1.w *= inv;
    reinterpret_cast<float4*>(p)[tid]       = v0;
    reinterpret_cast<float4*>(p)[256 + tid] = v1;
}

// ---------------------------------------------------------------------------
// Launch: LN stats -> normalize -> Q/KV GEMMs -> sim GEMM -> softmax ->
//         PV GEMM -> output GEMM. All graph-capturable (launches only).
// ---------------------------------------------------------------------------
extern "C" void kernel_launch(void* const* d_in, const int* /*in_sizes*/,
                              int /*n_in*/, void* d_out, int /*out_size*/) {
    const float* x   = (const float*)d_in[0];
    const float* g   = (const float*)d_in[1];
    const float* wq  = (const float*)d_in[2];
    const float* wkv = (const float*)d_in[3];
    const float* wo  = (const float*)d_in[4];
    float* out = (float*)d_out;

    float *xn, *q, *kv, *sim, *att;
    cudaGetSymbolAddress((void**)&xn,  g_xn);
    cudaGetSymbolAddress((void**)&q,   g_q);
    cudaGetSymbolAddress((void**)&kv,  g_kv);
    cudaGetSymbolAddress((void**)&sim, g_sim);
    cudaGetSymbolAddress((void**)&att, g_att);

    // LayerNorm over sequence axis
    ln_partial_kernel<<<dim3(DIM_ / 256, NCHUNK_, B_), 256>>>(x);
    ln_stats_kernel<<<dim3(DIM_ / 256, 1, B_), 256>>>(g);
    ln_norm_kernel<<<(B_ * N_ * DIM_ / 4) / 256, 256>>>(x);

    // q = xn @ wq * dhead^-0.5   [4096 x 512]
    sgemm_kernel<128, 128, 8, 8, 8, false>
        <<<dim3(INNER_ / 128, (B_ * N_) / 128, 1), 256>>>(
            xn, wq, q, DIM_, DIM_, INNER_, INNER_,
            0, 0, 0, 0, 0, 0, 0.125f);

    // kv = xn @ wkv              [4096 x 1024]
    sgemm_kernel<128, 128, 8, 8, 8, false>
        <<<dim3((2 * INNER_) / 128, (B_ * N_) / 128, 1), 256>>>(
            xn, wkv, kv, DIM_, DIM_, 2 * INNER_, 2 * INNER_,
            0, 0, 0, 0, 0, 0, 1.f);

    // sim[b,h] = q[b,:,h,:] @ k[b,:,h,:]^T   per (b,h): 2048x2048, K=64
    sgemm_kernel<128, 128, 8, 8, 8, true>
        <<<dim3(N_ / 128, N_ / 128, B_ * HEADS_), 256>>>(
            q, kv, sim, DHEAD_, INNER_, 2 * INNER_, N_,
            (long)N_ * INNER_, DHEAD_,
            (long)N_ * 2 * INNER_, DHEAD_,
            (long)HEADS_ * N_ * N_, (long)N_ * N_, 1.f);

    // softmax over last axis
    softmax_kernel<<<B_ * HEADS_ * N_, 256>>>(sim);

    // att[b,:,h,:] = P[b,h] @ v[b,:,h,:]    per (b,h): 2048x64, K=2048
    sgemm_kernel<128, 64, 8, 8, 8, false>
        <<<dim3(1, N_ / 128, B_ * HEADS_), 128>>>(
            sim, kv + INNER_, att, N_, N_, 2 * INNER_, INNER_,
            (long)HEADS_ * N_ * N_, (long)N_ * N_,
            (long)N_ * 2 * INNER_, DHEAD_,
            (long)N_ * INNER_, DHEAD_, 1.f);

    // out = att @ wo             [4096 x 1024]
    sgemm_kernel<128, 128, 8, 8, 8, false>
        <<<dim3(DIM_ / 128, (B_ * N_) / 128, 1), 256>>>(
            att, wo, out, INNER_, INNER_, DIM_, DIM_,
            0, 0, 0, 0, 0, 0, 1.f);
}

// round 2
// speedup vs baseline: 1.7120x; 1.7120x over previous
#include <cuda_runtime.h>
#include <cuda_bf16.h>
#include <cstdint>

namespace {
constexpr int B_      = 2;
constexpr int N_      = 2048;
constexpr int DIM_    = 1024;
constexpr int HEADS_  = 8;
constexpr int DHEAD_  = 64;
constexpr int INNER_  = 512;
constexpr float EPS_  = 1e-5f;
constexpr int NCHUNK_ = 16;
constexpr int CH_     = N_ / NCHUNK_;
}

// Scratch
__device__ float g_xn [B_ * N_ * DIM_];
__device__ float g_q  [B_ * N_ * INNER_];
__device__ float g_kv [B_ * N_ * 2 * INNER_];
__device__ float g_att[B_ * N_ * INNER_];
__device__ float g_ps [B_ * NCHUNK_ * DIM_];
__device__ float g_pss[B_ * NCHUNK_ * DIM_];
__device__ float g_scale[B_ * DIM_];
__device__ float g_bias [B_ * DIM_];

// ---------------------------------------------------------------------------
// Helpers: bf16 split + mma.sync m16n8k16
// ---------------------------------------------------------------------------
__device__ __forceinline__ void split1(float x, __nv_bfloat16& h, __nv_bfloat16& l) {
    h = __float2bfloat16(x);
    l = __float2bfloat16(x - __bfloat162float(h));
}

__device__ __forceinline__ void split2(float x, float y, uint32_t& h, uint32_t& l) {
    __nv_bfloat16 hx, lx, hy, ly;
    split1(x, hx, lx);
    split1(y, hy, ly);
    __nv_bfloat162 hp(hx, hy), lp(lx, ly);
    h = *reinterpret_cast<uint32_t*>(&hp);
    l = *reinterpret_cast<uint32_t*>(&lp);
}

__device__ __forceinline__ uint32_t lds32(const __nv_bfloat16* p) {
    return *reinterpret_cast<const uint32_t*>(p);
}

__device__ __forceinline__ void mma16816(float* c, const uint32_t* a, const uint32_t* b) {
    asm volatile(
        "mma.sync.aligned.m16n8k16.row.col.f32.bf16.bf16.f32 "
        "{%0,%1,%2,%3},{%4,%5,%6,%7},{%8,%9},{%0,%1,%2,%3};\n"
        : "+f"(c[0]), "+f"(c[1]), "+f"(c[2]), "+f"(c[3])
        : "r"(a[0]), "r"(a[1]), "r"(a[2]), "r"(a[3]), "r"(b[0]), "r"(b[1]));
}

// ---------------------------------------------------------------------------
// LayerNorm over sequence axis (axis=1)
// ---------------------------------------------------------------------------
__global__ void ln_partial_kernel(const float* __restrict__ x) {
    int d = blockIdx.x * blockDim.x + threadIdx.x;
    int c = blockIdx.y;
    int b = blockIdx.z;
    const float* px = x + ((size_t)b * N_ + (size_t)c * CH_) * DIM_ + d;
    float s = 0.f, ss = 0.f;
#pragma unroll 4
    for (int n = 0; n < CH_; n++) {
        float v = px[(size_t)n * DIM_];
        s += v;
        ss += v * v;
    }
    size_t o = ((size_t)b * NCHUNK_ + c) * DIM_ + d;
    g_ps[o]  = s;
    g_pss[o] = ss;
}

__global__ void ln_stats_kernel(const float* __restrict__ g) {
    int d = blockIdx.x * blockDim.x + threadIdx.x;
    int b = blockIdx.z;
    float s = 0.f, ss = 0.f;
#pragma unroll
    for (int c = 0; c < NCHUNK_; c++) {
        size_t o = ((size_t)b * NCHUNK_ + c) * DIM_ + d;
        s += g_ps[o];
        ss += g_pss[o];
    }
    float mean = s * (1.f / N_);
    float var  = fmaf(-mean, mean, ss * (1.f / N_));
    float sc   = rsqrtf(var + EPS_) * g[d];
    g_scale[b * DIM_ + d] = sc;
    g_bias[b * DIM_ + d]  = -mean * sc;
}

__global__ void ln_norm_kernel(const float* __restrict__ x) {
    int i = blockIdx.x * blockDim.x + threadIdx.x;
    int elem = i * 4;
    int d = elem & (DIM_ - 1);
    int b = elem / (N_ * DIM_);
    float4 xv = reinterpret_cast<const float4*>(x)[i];
    float4 sc = *reinterpret_cast<const float4*>(&g_scale[b * DIM_ + d]);
    float4 bi = *reinterpret_cast<const float4*>(&g_bias[b * DIM_ + d]);
    float4 r;
    r.x = fmaf(xv.x, sc.x, bi.x);
    r.y = fmaf(xv.y, sc.y, bi.y);
    r.z = fmaf(xv.z, sc.z, bi.z);
    r.w = fmaf(xv.w, sc.w, bi.w);
    reinterpret_cast<float4*>(g_xn)[i] = r;
}

// ---------------------------------------------------------------------------
// Split-bf16 tensor-core GEMM: C[M,N] = alpha * A[M,K] @ B[K,N], fp32 in/out.
// Tile 128x128, k-chunk 32, 8 warps (4x2), warp tile 32x64.
// A/B converted to bf16 hi/lo at staging time (3 mma per logical mma).
// M = gridDim.y*128, all dims multiples of tile sizes.
// ---------------------------------------------------------------------------
__global__ void __launch_bounds__(256)
gemm_bf16x2(const float* __restrict__ A, const float* __restrict__ B,
            float* __restrict__ C, int K, int N, float alpha) {
    __shared__ __nv_bfloat16 sAh[128 * 40], sAl[128 * 40];
    __shared__ __nv_bfloat16 sBh[128 * 40], sBl[128 * 40];  // Bt: [n][k]

    const int tid  = threadIdx.x;
    const int lane = tid & 31;
    const int w    = tid >> 5;
    const int wm   = w >> 1;
    const int wn   = w & 1;
    const int g    = lane >> 2;
    const int t4   = lane & 3;

    const int row0 = blockIdx.y * 128;
    const int col0 = blockIdx.x * 128;

    float c[2][8][4];
#pragma unroll
    for (int mi = 0; mi < 2; mi++)
#pragma unroll
        for (int ni = 0; ni < 8; ni++)
#pragma unroll
            for (int j = 0; j < 4; j++) c[mi][ni][j] = 0.f;

    for (int kc = 0; kc < K; kc += 32) {
        // Stage A tile (128 x 32) with on-the-fly split
#pragma unroll
        for (int it = 0; it < 4; it++) {
            int i = tid + it * 256;
            int r = i >> 3, cq = (i & 7) << 2;
            float4 v = *reinterpret_cast<const float4*>(
                A + (size_t)(row0 + r) * K + kc + cq);
            uint32_t h0, l0, h1, l1;
            split2(v.x, v.y, h0, l0);
            split2(v.z, v.w, h1, l1);
            *reinterpret_cast<uint32_t*>(&sAh[r * 40 + cq])     = h0;
            *reinterpret_cast<uint32_t*>(&sAh[r * 40 + cq + 2]) = h1;
            *reinterpret_cast<uint32_t*>(&sAl[r * 40 + cq])     = l0;
            *reinterpret_cast<uint32_t*>(&sAl[r * 40 + cq + 2]) = l1;
        }
        // Stage B tile (32 x 128), transposed into Bt[n][k]
#pragma unroll
        for (int it = 0; it < 4; it++) {
            int i = tid + it * 256;
            int kr = i >> 5, cq = (i & 31) << 2;
            float4 v = *reinterpret_cast<const float4*>(
                B + (size_t)(kc + kr) * N + col0 + cq);
            float vv[4] = {v.x, v.y, v.z, v.w};
#pragma unroll
            for (int j = 0; j < 4; j++) {
                __nv_bfloat16 h, l;
                split1(vv[j], h, l);
                sBh[(cq + j) * 40 + kr] = h;
                sBl[(cq + j) * 40 + kr] = l;
            }
        }
        __syncthreads();

#pragma unroll
        for (int ks = 0; ks < 2; ks++) {
            int k0 = ks * 16;
            uint32_t aH[2][4], aL[2][4];
#pragma unroll
            for (int mi = 0; mi < 2; mi++) {
                int r = 32 * wm + 16 * mi + g;
                aH[mi][0] = lds32(&sAh[r * 40 + k0 + 2 * t4]);
                aH[mi][1] = lds32(&sAh[(r + 8) * 40 + k0 + 2 * t4]);
                aH[mi][2] = lds32(&sAh[r * 40 + k0 + 2 * t4 + 8]);
                aH[mi][3] = lds32(&sAh[(r + 8) * 40 + k0 + 2 * t4 + 8]);
                aL[mi][0] = lds32(&sAl[r * 40 + k0 + 2 * t4]);
                aL[mi][1] = lds32(&sAl[(r + 8) * 40 + k0 + 2 * t4]);
                aL[mi][2] = lds32(&sAl[r * 40 + k0 + 2 * t4 + 8]);
                aL[mi][3] = lds32(&sAl[(r + 8) * 40 + k0 + 2 * t4 + 8]);
            }
#pragma unroll
            for (int ni = 0; ni < 8; ni++) {
                int cb = 64 * wn + 8 * ni + g;
                uint32_t bH[2], bL[2];
                bH[0] = lds32(&sBh[cb * 40 + k0 + 2 * t4]);
                bH[1] = lds32(&sBh[cb * 40 + k0 + 2 * t4 + 8]);
                bL[0] = lds32(&sBl[cb * 40 + k0 + 2 * t4]);
                bL[1] = lds32(&sBl[cb * 40 + k0 + 2 * t4 + 8]);
#pragma unroll
                for (int mi = 0; mi < 2; mi++) {
                    mma16816(c[mi][ni], aH[mi], bH);
                    mma16816(c[mi][ni], aH[mi], bL);
                    mma16816(c[mi][ni], aL[mi], bH);
                }
            }
        }
        __syncthreads();
    }

    // Epilogue
#pragma unroll
    for (int mi = 0; mi < 2; mi++) {
        int rA = row0 + 32 * wm + 16 * mi + g;
        int rB = rA + 8;
#pragma unroll
        for (int ni = 0; ni < 8; ni++) {
            int col = col0 + 64 * wn + 8 * ni + 2 * t4;
            float2 v0 = {c[mi][ni][0] * alpha, c[mi][ni][1] * alpha};
            float2 v1 = {c[mi][ni][2] * alpha, c[mi][ni][3] * alpha};
            *reinterpret_cast<float2*>(&C[(size_t)rA * N + col]) = v0;
            *reinterpret_cast<float2*>(&C[(size_t)rB * N + col]) = v1;
        }
    }
}

// ---------------------------------------------------------------------------
// Flash attention. One CTA per (q-tile 128, head, batch). d=64, 16 kv tiles
// of 128. Split-bf16 mma for QK^T and PV; online softmax; P in smem bf16 hi/lo.
// ---------------------------------------------------------------------------
namespace {
constexpr int QSS = 72;    // Q/K smem stride (bf16 elems)
constexpr int VSS = 136;   // Vt / P smem stride
// byte offsets into dynamic smem
constexpr int OFF_QH = 0;
constexpr int OFF_QL = 18432;
constexpr int OFF_KH = 36864;
constexpr int OFF_KL = 55296;
constexpr int OFF_VH = 73728;
constexpr int OFF_VL = 91136;
constexpr int OFF_PH = 108544;
constexpr int OFF_PL = 143360;
constexpr int OFF_ST = 178176;
constexpr int FLASH_SMEM = 181760;
}

__global__ void __launch_bounds__(256, 1)
flash_kernel(const float* __restrict__ q, const float* __restrict__ kv,
             float* __restrict__ att) {
    extern __shared__ char sm_[];
    __nv_bfloat16* sQh = (__nv_bfloat16*)(sm_ + OFF_QH);
    __nv_bfloat16* sQl = (__nv_bfloat16*)(sm_ + OFF_QL);
    __nv_bfloat16* sKh = (__nv_bfloat16*)(sm_ + OFF_KH);
    __nv_bfloat16* sKl = (__nv_bfloat16*)(sm_ + OFF_KL);
    __nv_bfloat16* sVh = (__nv_bfloat16*)(sm_ + OFF_VH);
    __nv_bfloat16* sVl = (__nv_bfloat16*)(sm_ + OFF_VL);
    __nv_bfloat16* sPh = (__nv_bfloat16*)(sm_ + OFF_PH);
    __nv_bfloat16* sPl = (__nv_bfloat16*)(sm_ + OFF_PL);
    float* sM    = (float*)(sm_ + OFF_ST);
    float* sL    = sM + 128;
    float* sAl_  = sM + 256;
    float* sWmax = sM + 384;   // [2][128]
    float* sWsum = sM + 640;   // [2][128]

    const int tid  = threadIdx.x;
    const int lane = tid & 31;
    const int w    = tid >> 5;
    const int wm   = w >> 1;
    const int wn   = w & 1;
    const int g    = lane >> 2;
    const int t4   = lane & 3;

    const int qt = blockIdx.x;
    const int h  = blockIdx.y;
    const int b  = blockIdx.z;

    const float* qb = q + ((size_t)(b * N_ + qt * 128)) * INNER_ + h * DHEAD_;

    // Init stats + stage Q (split bf16)
    if (tid < 128) {
        sM[tid] = -1e30f;
        sL[tid] = 0.f;
    }
#pragma unroll
    for (int it = 0; it < 8; it++) {
        int i = tid + it * 256;
        int r = i >> 4, dq = (i & 15) << 2;
        float4 v = *reinterpret_cast<const float4*>(qb + (size_t)r * INNER_ + dq);
        uint32_t h0, l0, h1, l1;
        split2(v.x, v.y, h0, l0);
        split2(v.z, v.w, h1, l1);
        *reinterpret_cast<uint32_t*>(&sQh[r * QSS + dq])     = h0;
        *reinterpret_cast<uint32_t*>(&sQh[r * QSS + dq + 2]) = h1;
        *reinterpret_cast<uint32_t*>(&sQl[r * QSS + dq])     = l0;
        *reinterpret_cast<uint32_t*>(&sQl[r * QSS + dq + 2]) = l1;
    }

    float o[8][4];
#pragma unroll
    for (int ni = 0; ni < 8; ni++)
#pragma unroll
        for (int j = 0; j < 4; j++) o[ni][j] = 0.f;

    for (int kt = 0; kt < 16; kt++) {
        __syncthreads();  // smem K/V/P reuse safe

        const float* kb = kv + ((size_t)(b * N_ + kt * 128)) * (2 * INNER_) + h * DHEAD_;
        const float* vb = kb + INNER_;
        // Stage K (row-major keys x d) and V (transposed: d x keys)
#pragma unroll
        for (int it = 0; it < 8; it++) {
            int i = tid + it * 256;
            int r = i >> 4, dq = (i & 15) << 2;
            float4 v = *reinterpret_cast<const float4*>(kb + (size_t)r * (2 * INNER_) + dq);
            uint32_t h0, l0, h1, l1;
            split2(v.x, v.y, h0, l0);
            split2(v.z, v.w, h1, l1);
            *reinterpret_cast<uint32_t*>(&sKh[r * QSS + dq])     = h0;
            *reinterpret_cast<uint32_t*>(&sKh[r * QSS + dq + 2]) = h1;
            *reinterpret_cast<uint32_t*>(&sKl[r * QSS + dq])     = l0;
            *reinterpret_cast<uint32_t*>(&sKl[r * QSS + dq + 2]) = l1;

            float4 vv = *reinterpret_cast<const float4*>(vb + (size_t)r * (2 * INNER_) + dq);
            float va[4] = {vv.x, vv.y, vv.z, vv.w};
#pragma unroll
            for (int j = 0; j < 4; j++) {
                __nv_bfloat16 hh, ll;
                split1(va[j], hh, ll);
                sVh[(dq + j) * VSS + r] = hh;
                sVl[(dq + j) * VSS + r] = ll;
            }
        }
        __syncthreads();

        // ---- S = Q @ K^T (warp tile 32 x 64) ----
        float s[2][8][4];
#pragma unroll
        for (int mi = 0; mi < 2; mi++)
#pragma unroll
            for (int ni = 0; ni < 8; ni++)
#pragma unroll
                for (int j = 0; j < 4; j++) s[mi][ni][j] = 0.f;

#pragma unroll
        for (int kk = 0; kk < 4; kk++) {
            int k0 = kk * 16;
            uint32_t aH[2][4], aL[2][4];
#pragma unroll
            for (int mi = 0; mi < 2; mi++) {
                int r = 32 * wm + 16 * mi + g;
                aH[mi][0] = lds32(&sQh[r * QSS + k0 + 2 * t4]);
                aH[mi][1] = lds32(&sQh[(r + 8) * QSS + k0 + 2 * t4]);
                aH[mi][2] = lds32(&sQh[r * QSS + k0 + 2 * t4 + 8]);
                aH[mi][3] = lds32(&sQh[(r + 8) * QSS + k0 + 2 * t4 + 8]);
                aL[mi][0] = lds32(&sQl[r * QSS + k0 + 2 * t4]);
                aL[mi][1] = lds32(&sQl[(r + 8) * QSS + k0 + 2 * t4]);
                aL[mi][2] = lds32(&sQl[r * QSS + k0 + 2 * t4 + 8]);
                aL[mi][3] = lds32(&sQl[(r + 8) * QSS + k0 + 2 * t4 + 8]);
            }
#pragma unroll
            for (int ni = 0; ni < 8; ni++) {
                int cb = 64 * wn + 8 * ni + g;
                uint32_t bH[2], bL[2];
                bH[0] = lds32(&sKh[cb * QSS + k0 + 2 * t4]);
                bH[1] = lds32(&sKh[cb * QSS + k0 + 2 * t4 + 8]);
                bL[0] = lds32(&sKl[cb * QSS + k0 + 2 * t4]);
                bL[1] = lds32(&sKl[cb * QSS + k0 + 2 * t4 + 8]);
#pragma unroll
                for (int mi = 0; mi < 2; mi++) {
                    mma16816(s[mi][ni], aH[mi], bH);
                    mma16816(s[mi][ni], aH[mi], bL);
                    mma16816(s[mi][ni], aL[mi], bH);
                }
            }
        }

        // ---- online softmax ----
        float mxA[2], mxB[2];
#pragma unroll
        for (int mi = 0; mi < 2; mi++) {
            float ma = -1e30f, mb = -1e30f;
#pragma unroll
            for (int ni = 0; ni < 8; ni++) {
                ma = fmaxf(ma, fmaxf(s[mi][ni][0], s[mi][ni][1]));
                mb = fmaxf(mb, fmaxf(s[mi][ni][2], s[mi][ni][3]));
            }
            ma = fmaxf(ma, __shfl_xor_sync(0xffffffffu, ma, 1));
            ma = fmaxf(ma, __shfl_xor_sync(0xffffffffu, ma, 2));
            mb = fmaxf(mb, __shfl_xor_sync(0xffffffffu, mb, 1));
            mb = fmaxf(mb, __shfl_xor_sync(0xffffffffu, mb, 2));
            mxA[mi] = ma;
            mxB[mi] = mb;
            if (t4 == 0) {
                int rA = 32 * wm + 16 * mi + g;
                sWmax[wn * 128 + rA]     = ma;
                sWmax[wn * 128 + rA + 8] = mb;
            }
        }
        __syncthreads();

#pragma unroll
        for (int mi = 0; mi < 2; mi++) {
            int rA = 32 * wm + 16 * mi + g;
            int rB = rA + 8;
            float nmA = fmaxf(sM[rA], fmaxf(sWmax[rA], sWmax[128 + rA]));
            float nmB = fmaxf(sM[rB], fmaxf(sWmax[rB], sWmax[128 + rB]));
            float suA = 0.f, suB = 0.f;
#pragma unroll
            for (int ni = 0; ni < 8; ni++) {
                s[mi][ni][0] = __expf(s[mi][ni][0] - nmA);
                s[mi][ni][1] = __expf(s[mi][ni][1] - nmA);
                s[mi][ni][2] = __expf(s[mi][ni][2] - nmB);
                s[mi][ni][3] = __expf(s[mi][ni][3] - nmB);
                suA += s[mi][ni][0] + s[mi][ni][1];
                suB += s[mi][ni][2] + s[mi][ni][3];
                // store P (split) to smem
                uint32_t hp, lp;
                int col = 64 * wn + 8 * ni + 2 * t4;
                split2(s[mi][ni][0], s[mi][ni][1], hp, lp);
                *reinterpret_cast<uint32_t*>(&sPh[rA * VSS + col]) = hp;
                *reinterpret_cast<uint32_t*>(&sPl[rA * VSS + col]) = lp;
                split2(s[mi][ni][2], s[mi][ni][3], hp, lp);
                *reinterpret_cast<uint32_t*>(&sPh[rB * VSS + col]) = hp;
                *reinterpret_cast<uint32_t*>(&sPl[rB * VSS + col]) = lp;
            }
            suA += __shfl_xor_sync(0xffffffffu, suA, 1);
            suA += __shfl_xor_sync(0xffffffffu, suA, 2);
            suB += __shfl_xor_sync(0xffffffffu, suB, 1);
            suB += __shfl_xor_sync(0xffffffffu, suB, 2);
            if (t4 == 0) {
                sWsum[wn * 128 + rA] = suA;
                sWsum[wn * 128 + rB] = suB;
            }
        }
        __syncthreads();

        // owners update m, l, alpha
        if (wn == 0 && t4 == 0) {
#pragma unroll
            for (int mi = 0; mi < 2; mi++) {
#pragma unroll
                for (int half = 0; half < 2; half++) {
                    int r = 32 * wm + 16 * mi + half * 8 + g;
                    float om = sM[r];
                    float nm = fmaxf(om, fmaxf(sWmax[r], sWmax[128 + r]));
                    float a  = __expf(om - nm);
                    sL[r]   = a * sL[r] + sWsum[r] + sWsum[128 + r];
                    sM[r]   = nm;
                    sAl_[r] = a;
                }
            }
        }
        __syncthreads();

        // ---- O = alpha*O + P @ V (warp tile 16 x 64) ----
        int r0 = 16 * w;
        float a0 = sAl_[r0 + g];
        float a1 = sAl_[r0 + 8 + g];
#pragma unroll
        for (int ni = 0; ni < 8; ni++) {
            o[ni][0] *= a0;
            o[ni][1] *= a0;
            o[ni][2] *= a1;
            o[ni][3] *= a1;
        }
#pragma unroll
        for (int kk = 0; kk < 8; kk++) {
            int k0 = kk * 16;
            uint32_t aH[4], aL[4];
            aH[0] = lds32(&sPh[(r0 + g) * VSS + k0 + 2 * t4]);
            aH[1] = lds32(&sPh[(r0 + g + 8) * VSS + k0 + 2 * t4]);
            aH[2] = lds32(&sPh[(r0 + g) * VSS + k0 + 2 * t4 + 8]);
            aH[3] = lds32(&sPh[(r0 + g + 8) * VSS + k0 + 2 * t4 + 8]);
            aL[0] = lds32(&sPl[(r0 + g) * VSS + k0 + 2 * t4]);
            aL[1] = lds32(&sPl[(r0 + g + 8) * VSS + k0 + 2 * t4]);
            aL[2] = lds32(&sPl[(r0 + g) * VSS + k0 + 2 * t4 + 8]);
            aL[3] = lds32(&sPl[(r0 + g + 8) * VSS + k0 + 2 * t4 + 8]);
#pragma unroll
            for (int ni = 0; ni < 8; ni++) {
                uint32_t bH[2], bL[2];
                bH[0] = lds32(&sVh[(8 * ni + g) * VSS + k0 + 2 * t4]);
                bH[1] = lds32(&sVh[(8 * ni + g) * VSS + k0 + 2 * t4 + 8]);
                bL[0] = lds32(&sVl[(8 * ni + g) * VSS + k0 + 2 * t4]);
                bL[1] = lds32(&sVl[(8 * ni + g) * VSS + k0 + 2 * t4 + 8]);
                mma16816(o[ni], aH, bH);
                mma16816(o[ni], aH, bL);
                mma16816(o[ni], aL, bH);
            }
        }
    }

    // Epilogue: normalize by l, write att fp32
    int r0 = 16 * w;
    int rA = r0 + g, rB = r0 + 8 + g;
    float iA = 1.f / sL[rA];
    float iB = 1.f / sL[rB];
    float* ob = att + ((size_t)(b * N_ + qt * 128)) * INNER_ + h * DHEAD_;
#pragma unroll
    for (int ni = 0; ni < 8; ni++) {
        int d = 8 * ni + 2 * t4;
        float2 v0 = {o[ni][0] * iA, o[ni][1] * iA};
        float2 v1 = {o[ni][2] * iB, o[ni][3] * iB};
        *reinterpret_cast<float2*>(&ob[(size_t)rA * INNER_ + d]) = v0;
        *reinterpret_cast<float2*>(&ob[(size_t)rB * INNER_ + d]) = v1;
    }
}

// ---------------------------------------------------------------------------
extern "C" void kernel_launch(void* const* d_in, const int* /*in_sizes*/,
                              int /*n_in*/, void* d_out, int /*out_size*/) {
    const float* x   = (const float*)d_in[0];
    const float* g   = (const float*)d_in[1];
    const float* wq  = (const float*)d_in[2];
    const float* wkv = (const float*)d_in[3];
    const float* wo  = (const float*)d_in[4];
    float* out = (float*)d_out;

    float *xn, *qp, *kvp, *attp;
    cudaGetSymbolAddress((void**)&xn,   g_xn);
    cudaGetSymbolAddress((void**)&qp,   g_q);
    cudaGetSymbolAddress((void**)&kvp,  g_kv);
    cudaGetSymbolAddress((void**)&attp, g_att);

    cudaFuncSetAttribute(flash_kernel,
                         cudaFuncAttributeMaxDynamicSharedMemorySize, FLASH_SMEM);

    // LayerNorm over sequence axis
    ln_partial_kernel<<<dim3(DIM_ / 256, NCHUNK_, B_), 256>>>(x);
    ln_stats_kernel<<<dim3(DIM_ / 256, 1, B_), 256>>>(g);
    ln_norm_kernel<<<(B_ * N_ * DIM_ / 4) / 256, 256>>>(x);

    // q = xn @ wq * dhead^-0.5
    gemm_bf16x2<<<dim3(INNER_ / 128, (B_ * N_) / 128), 256>>>(
        xn, wq, qp, DIM_, INNER_, 0.125f);
    // kv = xn @ wkv
    gemm_bf16x2<<<dim3((2 * INNER_) / 128, (B_ * N_) / 128), 256>>>(
        xn, wkv, kvp, DIM_, 2 * INNER_, 1.f);
    // fused attention -> att
    flash_kernel<<<dim3(N_ / 128, HEADS_, B_), 256, FLASH_SMEM>>>(qp, kvp, attp);
    // out = att @ wo
    gemm_bf16x2<<<dim3(DIM_ / 128, (B_ * N_) / 128), 256>>>(
        attp, wo, out, INNER_, DIM_, 1.f);
}

// round 3
// speedup vs baseline: 3.6438x; 2.1284x over previous
#include <cuda_runtime.h>
#include <cuda_bf16.h>
#include <cstdint>

namespace {
constexpr int B_      = 2;
constexpr int N_      = 2048;
constexpr int DIM_    = 1024;
constexpr int HEADS_  = 8;
constexpr int DHEAD_  = 64;
constexpr int INNER_  = 512;
constexpr int QKVN_   = 1536;   // fused q|k|v columns
constexpr float EPS_  = 1e-5f;
constexpr int NCHUNK_ = 16;
constexpr int CH_     = N_ / NCHUNK_;
}

// Scratch (bf16 hi/lo pairs everywhere)
__device__ __nv_bfloat16 g_xnh [B_ * N_ * DIM_],  g_xnl [B_ * N_ * DIM_];
__device__ __nv_bfloat16 g_qkvh[B_ * N_ * QKVN_], g_qkvl[B_ * N_ * QKVN_];
__device__ __nv_bfloat16 g_atth[B_ * N_ * INNER_],g_attl[B_ * N_ * INNER_];
__device__ __nv_bfloat16 g_wqkvh[DIM_ * QKVN_],   g_wqkvl[DIM_ * QKVN_];
__device__ __nv_bfloat16 g_woh [INNER_ * DIM_],   g_wol [INNER_ * DIM_];
__device__ float g_ps [B_ * NCHUNK_ * DIM_];
__device__ float g_pss[B_ * NCHUNK_ * DIM_];
__device__ float g_scale[B_ * DIM_];
__device__ float g_bias [B_ * DIM_];

// ---------------------------------------------------------------------------
// Helpers
// ---------------------------------------------------------------------------
__device__ __forceinline__ void split2(float x, float y, uint32_t& h, uint32_t& l) {
    __nv_bfloat16 hx = __float2bfloat16(x);
    __nv_bfloat16 hy = __float2bfloat16(y);
    __nv_bfloat16 lx = __float2bfloat16(x - __bfloat162float(hx));
    __nv_bfloat16 ly = __float2bfloat16(y - __bfloat162float(hy));
    __nv_bfloat162 hp(hx, hy), lp(lx, ly);
    h = *reinterpret_cast<uint32_t*>(&hp);
    l = *reinterpret_cast<uint32_t*>(&lp);
}

__device__ __forceinline__ void mma16816(float* c, const uint32_t* a, const uint32_t* b) {
    asm volatile(
        "mma.sync.aligned.m16n8k16.row.col.f32.bf16.bf16.f32 "
        "{%0,%1,%2,%3},{%4,%5,%6,%7},{%8,%9},{%0,%1,%2,%3};\n"
        : "+f"(c[0]), "+f"(c[1]), "+f"(c[2]), "+f"(c[3])
        : "r"(a[0]), "r"(a[1]), "r"(a[2]), "r"(a[3]), "r"(b[0]), "r"(b[1]));
}

__device__ __forceinline__ uint32_t smem_u32(const void* p) {
    return (uint32_t)__cvta_generic_to_shared(p);
}
__device__ __forceinline__ void ldm_x4(uint32_t* r, uint32_t a) {
    asm volatile("ldmatrix.sync.aligned.m8n8.x4.shared.b16 {%0,%1,%2,%3},[%4];"
                 : "=r"(r[0]), "=r"(r[1]), "=r"(r[2]), "=r"(r[3]) : "r"(a));
}
__device__ __forceinline__ void ldm_x4_t(uint32_t* r, uint32_t a) {
    asm volatile("ldmatrix.sync.aligned.m8n8.x4.trans.shared.b16 {%0,%1,%2,%3},[%4];"
                 : "=r"(r[0]), "=r"(r[1]), "=r"(r[2]), "=r"(r[3]) : "r"(a));
}
__device__ __forceinline__ void cp16(uint32_t dst, const void* src) {
    asm volatile("cp.async.cg.shared.global [%0],[%1],16;\n" :: "r"(dst), "l"(src));
}
__device__ __forceinline__ void cp_commit() {
    asm volatile("cp.async.commit_group;\n" ::: "memory");
}
__device__ __forceinline__ void cp_wait1() {
    asm volatile("cp.async.wait_group 1;\n" ::: "memory");
}

// Swizzles (16B chunk granularity), conflict-free for staging + ldmatrix
__device__ __forceinline__ uint32_t swzA(int r, int c) {   // 64B rows, c in [0,4)
    return (uint32_t)(r * 64 + ((c ^ ((r >> 1) & 3)) << 4));
}
__device__ __forceinline__ uint32_t swzB(int r, int c) {   // 256B rows, c in [0,16)
    return (uint32_t)(r * 256 + ((c ^ (r & 7)) << 4));
}
__device__ __forceinline__ uint32_t swzF(int r, int c) {   // 128B rows, c in [0,8)
    return (uint32_t)(r * 128 + ((c ^ (r & 7)) << 4));
}

// ---------------------------------------------------------------------------
// LayerNorm over sequence axis (axis=1)
// ---------------------------------------------------------------------------
__global__ void ln_partial_kernel(const float* __restrict__ x) {
    int d = blockIdx.x * blockDim.x + threadIdx.x;
    int c = blockIdx.y;
    int b = blockIdx.z;
    const float* px = x + ((size_t)b * N_ + (size_t)c * CH_) * DIM_ + d;
    float s = 0.f, ss = 0.f;
#pragma unroll 4
    for (int n = 0; n < CH_; n++) {
        float v = px[(size_t)n * DIM_];
        s += v;
        ss += v * v;
    }
    size_t o = ((size_t)b * NCHUNK_ + c) * DIM_ + d;
    g_ps[o]  = s;
    g_pss[o] = ss;
}

__global__ void ln_stats_kernel(const float* __restrict__ g) {
    int d = blockIdx.x * blockDim.x + threadIdx.x;
    int b = blockIdx.z;
    float s = 0.f, ss = 0.f;
#pragma unroll
    for (int c = 0; c < NCHUNK_; c++) {
        size_t o = ((size_t)b * NCHUNK_ + c) * DIM_ + d;
        s += g_ps[o];
        ss += g_pss[o];
    }
    float mean = s * (1.f / N_);
    float var  = fmaf(-mean, mean, ss * (1.f / N_));
    float sc   = rsqrtf(var + EPS_) * g[d];
    g_scale[b * DIM_ + d] = sc;
    g_bias[b * DIM_ + d]  = -mean * sc;
}

__global__ void ln_norm_kernel(const float* __restrict__ x) {
    int i = blockIdx.x * blockDim.x + threadIdx.x;
    int elem = i * 4;
    int d = elem & (DIM_ - 1);
    int b = elem / (N_ * DIM_);
    float4 xv = reinterpret_cast<const float4*>(x)[i];
    float4 sc = *reinterpret_cast<const float4*>(&g_scale[b * DIM_ + d]);
    float4 bi = *reinterpret_cast<const float4*>(&g_bias[b * DIM_ + d]);
    float rx = fmaf(xv.x, sc.x, bi.x);
    float ry = fmaf(xv.y, sc.y, bi.y);
    float rz = fmaf(xv.z, sc.z, bi.z);
    float rw = fmaf(xv.w, sc.w, bi.w);
    uint32_t h0, l0, h1, l1;
    split2(rx, ry, h0, l0);
    split2(rz, rw, h1, l1);
    uint2 hh = {h0, h1}, ll = {l0, l1};
    reinterpret_cast<uint2*>(g_xnh)[i] = hh;
    reinterpret_cast<uint2*>(g_xnl)[i] = ll;
}

// ---------------------------------------------------------------------------
// Weight conversion (0.125 folded into q columns)
// ---------------------------------------------------------------------------
__global__ void conv_qkv_kernel(const float* __restrict__ wq,
                                const float* __restrict__ wkv) {
    int i = blockIdx.x * blockDim.x + threadIdx.x;
    int elem = i * 4;
    int row = elem / QKVN_, col = elem % QKVN_;
    float4 v;
    if (col < INNER_) {
        v = *reinterpret_cast<const float4*>(wq + (size_t)row * INNER_ + col);
        v.x *= 0.125f; v.y *= 0.125f; v.z *= 0.125f; v.w *= 0.125f;
    } else {
        v = *reinterpret_cast<const float4*>(wkv + (size_t)row * (2 * INNER_) + col - INNER_);
    }
    uint32_t h0, l0, h1, l1;
    split2(v.x, v.y, h0, l0);
    split2(v.z, v.w, h1, l1);
    uint2 hh = {h0, h1}, ll = {l0, l1};
    reinterpret_cast<uint2*>(g_wqkvh)[i] = hh;
    reinterpret_cast<uint2*>(g_wqkvl)[i] = ll;
}

__global__ void conv_wo_kernel(const float* __restrict__ wo) {
    int i = blockIdx.x * blockDim.x + threadIdx.x;
    float4 v = reinterpret_cast<const float4*>(wo)[i];
    uint32_t h0, l0, h1, l1;
    split2(v.x, v.y, h0, l0);
    split2(v.z, v.w, h1, l1);
    uint2 hh = {h0, h1}, ll = {l0, l1};
    reinterpret_cast<uint2*>(g_woh)[i] = hh;
    reinterpret_cast<uint2*>(g_wol)[i] = ll;
}

// ---------------------------------------------------------------------------
// Split-bf16 tensor-core GEMM, cp.async double-buffered, ldmatrix operands.
// C[M,N] = A[M,K] @ B[K,N]; A,B given as bf16 hi/lo. 128x128 tile, BK=32.
// Stage layout (32KB): Ah 0 | Al 8192 | Bh 16384 | Bl 24576. Two stages.
// ---------------------------------------------------------------------------
template <bool SPLIT_OUT>
__global__ void __launch_bounds__(256, 2)
gemm_tc(const __nv_bfloat16* __restrict__ Ah, const __nv_bfloat16* __restrict__ Al,
        const __nv_bfloat16* __restrict__ Bh, const __nv_bfloat16* __restrict__ Bl,
        float* __restrict__ C, __nv_bfloat16* __restrict__ Ch,
        __nv_bfloat16* __restrict__ Cl, int K, int N) {
    extern __shared__ char sm_[];
    const uint32_t sb = smem_u32(sm_);
    const int tid = threadIdx.x, lane = tid & 31, w = tid >> 5;
    const int wm = w >> 1, wn = w & 1, g = lane >> 2, t4 = lane & 3;
    const int row0 = blockIdx.y * 128, col0 = blockIdx.x * 128;
    const int KT = K >> 5;

    const int ar = tid >> 2, ac = tid & 3;
    const int br = tid >> 4, bc = tid & 15;

    auto issue = [&](int kt) {
        const uint32_t st = sb + (uint32_t)(kt & 1) * 32768u;
        const __nv_bfloat16* pah = Ah + (size_t)(row0 + ar) * K + kt * 32 + ac * 8;
        const __nv_bfloat16* pal = Al + (size_t)(row0 + ar) * K + kt * 32 + ac * 8;
        cp16(st + swzA(ar, ac), pah);
        cp16(st + swzA(ar + 64, ac), pah + (size_t)64 * K);
        cp16(st + 8192u + swzA(ar, ac), pal);
        cp16(st + 8192u + swzA(ar + 64, ac), pal + (size_t)64 * K);
        const __nv_bfloat16* pbh = Bh + (size_t)(kt * 32 + br) * N + col0 + bc * 8;
        const __nv_bfloat16* pbl = Bl + (size_t)(kt * 32 + br) * N + col0 + bc * 8;
        cp16(st + 16384u + swzB(br, bc), pbh);
        cp16(st + 16384u + swzB(br + 16, bc), pbh + (size_t)16 * N);
        cp16(st + 24576u + swzB(br, bc), pbl);
        cp16(st + 24576u + swzB(br + 16, bc), pbl + (size_t)16 * N);
        cp_commit();
    };

    float acc[2][8][4];
#pragma unroll
    for (int mi = 0; mi < 2; mi++)
#pragma unroll
        for (int ni = 0; ni < 8; ni++)
#pragma unroll
            for (int j = 0; j < 4; j++) acc[mi][ni][j] = 0.f;

    issue(0);
    for (int kt = 0; kt < KT; kt++) {
        if (kt + 1 < KT) issue(kt + 1);
        else cp_commit();
        cp_wait1();
        __syncthreads();
        const uint32_t st = sb + (uint32_t)(kt & 1) * 32768u;
#pragma unroll
        for (int kk = 0; kk < 2; kk++) {
            uint32_t aH[2][4], aL[2][4];
            const int arow = 32 * wm + (lane & 15);
            const int ach  = 2 * kk + (lane >> 4);
#pragma unroll
            for (int mi = 0; mi < 2; mi++) {
                uint32_t off = swzA(arow + 16 * mi, ach);
                ldm_x4(aH[mi], st + off);
                ldm_x4(aL[mi], st + 8192u + off);
            }
            const int brow = 16 * kk + (lane & 7) + ((lane >> 3) & 1) * 8;
#pragma unroll
            for (int nn = 0; nn < 4; nn++) {
                const int bch = 8 * wn + 2 * nn + (lane >> 4);
                uint32_t off = swzB(brow, bch);
                uint32_t bh[4], bl[4];
                ldm_x4_t(bh, st + 16384u + off);
                ldm_x4_t(bl, st + 24576u + off);
#pragma unroll
                for (int sub = 0; sub < 2; sub++) {
                    const int ni = 2 * nn + sub;
#pragma unroll
                    for (int mi = 0; mi < 2; mi++) {
                        mma16816(acc[mi][ni], aH[mi], bh + 2 * sub);
                        mma16816(acc[mi][ni], aH[mi], bl + 2 * sub);
                        mma16816(acc[mi][ni], aL[mi], bh + 2 * sub);
                    }
                }
            }
        }
        __syncthreads();
    }

#pragma unroll
    for (int mi = 0; mi < 2; mi++) {
        int rA = row0 + 32 * wm + 16 * mi + g;
#pragma unroll
        for (int ni = 0; ni < 8; ni++) {
            int col = col0 + 64 * wn + 8 * ni + 2 * t4;
            if (SPLIT_OUT) {
                uint32_t h, l;
                split2(acc[mi][ni][0], acc[mi][ni][1], h, l);
                *reinterpret_cast<uint32_t*>(Ch + (size_t)rA * N + col) = h;
                *reinterpret_cast<uint32_t*>(Cl + (size_t)rA * N + col) = l;
                split2(acc[mi][ni][2], acc[mi][ni][3], h, l);
                *reinterpret_cast<uint32_t*>(Ch + (size_t)(rA + 8) * N + col) = h;
                *reinterpret_cast<uint32_t*>(Cl + (size_t)(rA + 8) * N + col) = l;
            } else {
                float2 v0 = {acc[mi][ni][0], acc[mi][ni][1]};
                float2 v1 = {acc[mi][ni][2], acc[mi][ni][3]};
                *reinterpret_cast<float2*>(C + (size_t)rA * N + col) = v0;
                *reinterpret_cast<float2*>(C + (size_t)(rA + 8) * N + col) = v1;
            }
        }
    }
}

// ---------------------------------------------------------------------------
// Flash attention: 128-row Q tile per CTA, d=64, 16 kv tiles of 128.
// Q staged once; K/V double-buffered via cp.async. P kept in registers.
// Smem: Qh 0 | Ql 16384 | stage0 @32768 | stage1 @98304 | stats @163840
// Stage: Kh 0 | Kl 16384 | Vh 32768 | Vl 49152  (64KB)
// ---------------------------------------------------------------------------
namespace { constexpr int FLASH_SMEM = 167424; }

__global__ void __launch_bounds__(256)
flash_kernel(const __nv_bfloat16* __restrict__ qkvh,
             const __nv_bfloat16* __restrict__ qkvl,
             __nv_bfloat16* __restrict__ atth,
             __nv_bfloat16* __restrict__ attl) {
    extern __shared__ char sm_[];
    const uint32_t sb = smem_u32(sm_);
    float* sM    = (float*)(sm_ + 163840);
    float* sL    = sM + 128;
    float* sAl_  = sM + 256;
    float* sWmax = sM + 384;   // [2][128]
    float* sWsum = sM + 640;   // [2][128]

    const int tid = threadIdx.x, lane = tid & 31, w = tid >> 5;
    const int wm = w >> 1, wn = w & 1, g = lane >> 2, t4 = lane & 3;
    const int qt = blockIdx.x, h = blockIdx.y, b = blockIdx.z;
    const size_t qrow0 = (size_t)(b * N_ + qt * 128);

    // stats init
    if (tid < 128) { sM[tid] = -1e30f; sL[tid] = 0.f; }

    // stage Q (goes into group 0 together with KV stage 0)
    {
        int r = tid >> 3, c = tid & 7;
        const __nv_bfloat16* ph = qkvh + (qrow0 + r) * QKVN_ + h * 64 + c * 8;
        const __nv_bfloat16* pl = qkvl + (qrow0 + r) * QKVN_ + h * 64 + c * 8;
#pragma unroll
        for (int it = 0; it < 4; it++) {
            uint32_t o = swzF(r + 32 * it, c);
            size_t go = (size_t)(32 * it) * QKVN_;
            cp16(sb + o, ph + go);
            cp16(sb + 16384u + o, pl + go);
        }
    }

    auto issueKV = [&](int kt) {
        const uint32_t st = sb + 32768u + (uint32_t)(kt & 1) * 65536u;
        int r = tid >> 3, c = tid & 7;
        size_t rowb = (size_t)(b * N_ + kt * 128);
        const __nv_bfloat16* pkh = qkvh + (rowb + r) * QKVN_ + 512 + h * 64 + c * 8;
        const __nv_bfloat16* pkl = qkvl + (rowb + r) * QKVN_ + 512 + h * 64 + c * 8;
#pragma unroll
        for (int it = 0; it < 4; it++) {
            uint32_t o = swzF(r + 32 * it, c);
            size_t go = (size_t)(32 * it) * QKVN_;
            cp16(st + o,           pkh + go);
            cp16(st + 16384u + o,  pkl + go);
            cp16(st + 32768u + o,  pkh + go + 512);   // V = K + 512 cols
            cp16(st + 49152u + o,  pkl + go + 512);
        }
        cp_commit();
    };

    issueKV(0);

    float o[2][8][4];
#pragma unroll
    for (int mi = 0; mi < 2; mi++)
#pragma unroll
        for (int ni = 0; ni < 8; ni++)
#pragma unroll
            for (int j = 0; j < 4; j++) o[mi][ni][j] = 0.f;

    for (int kt = 0; kt < 16; kt++) {
        if (kt + 1 < 16) issueKV(kt + 1);
        else cp_commit();
        cp_wait1();
        __syncthreads();                               // stage kt ready
        const uint32_t st = sb + 32768u + (uint32_t)(kt & 1) * 65536u;

        // ---- S = Q K^T ----
        float s[2][8][4];
#pragma unroll
        for (int mi = 0; mi < 2; mi++)
#pragma unroll
            for (int ni = 0; ni < 8; ni++)
#pragma unroll
                for (int j = 0; j < 4; j++) s[mi][ni][j] = 0.f;

#pragma unroll
        for (int kk = 0; kk < 4; kk++) {
            uint32_t aH[2][4], aL[2][4];
            const int arow = 32 * wm + (lane & 15);
            const int ach  = 2 * kk + (lane >> 4);
#pragma unroll
            for (int mi = 0; mi < 2; mi++) {
                uint32_t off = swzF(arow + 16 * mi, ach);
                ldm_x4(aH[mi], sb + off);
                ldm_x4(aL[mi], sb + 16384u + off);
            }
            const int krw = (lane & 7) + (lane >> 4) * 8;
            const int kch = 2 * kk + ((lane >> 3) & 1);
#pragma unroll
            for (int nn = 0; nn < 4; nn++) {
                uint32_t off = swzF(64 * wn + 16 * nn + krw, kch);
                uint32_t bh[4], bl[4];
                ldm_x4(bh, st + off);
                ldm_x4(bl, st + 16384u + off);
#pragma unroll
                for (int sub = 0; sub < 2; sub++) {
                    const int ni = 2 * nn + sub;
#pragma unroll
                    for (int mi = 0; mi < 2; mi++) {
                        mma16816(s[mi][ni], aH[mi], bh + 2 * sub);
                        mma16816(s[mi][ni], aH[mi], bl + 2 * sub);
                        mma16816(s[mi][ni], aL[mi], bh + 2 * sub);
                    }
                }
            }
        }

        // ---- row max ----
#pragma unroll
        for (int mi = 0; mi < 2; mi++) {
            float ma = -1e30f, mb = -1e30f;
#pragma unroll
            for (int ni = 0; ni < 8; ni++) {
                ma = fmaxf(ma, fmaxf(s[mi][ni][0], s[mi][ni][1]));
                mb = fmaxf(mb, fmaxf(s[mi][ni][2], s[mi][ni][3]));
            }
            ma = fmaxf(ma, __shfl_xor_sync(0xffffffffu, ma, 1));
            ma = fmaxf(ma, __shfl_xor_sync(0xffffffffu, ma, 2));
            mb = fmaxf(mb, __shfl_xor_sync(0xffffffffu, mb, 1));
            mb = fmaxf(mb, __shfl_xor_sync(0xffffffffu, mb, 2));
            if (t4 == 0) {
                int rA = 32 * wm + 16 * mi + g;
                sWmax[wn * 128 + rA]     = ma;
                sWmax[wn * 128 + rA + 8] = mb;
            }
        }
        __syncthreads();

        // ---- exp + partial sums (P stays in s) ----
#pragma unroll
        for (int mi = 0; mi < 2; mi++) {
            int rA = 32 * wm + 16 * mi + g;
            int rB = rA + 8;
            float nmA = fmaxf(sM[rA], fmaxf(sWmax[rA], sWmax[128 + rA]));
            float nmB = fmaxf(sM[rB], fmaxf(sWmax[rB], sWmax[128 + rB]));
            float suA = 0.f, suB = 0.f;
#pragma unroll
            for (int ni = 0; ni < 8; ni++) {
                s[mi][ni][0] = __expf(s[mi][ni][0] - nmA);
                s[mi][ni][1] = __expf(s[mi][ni][1] - nmA);
                s[mi][ni][2] = __expf(s[mi][ni][2] - nmB);
                s[mi][ni][3] = __expf(s[mi][ni][3] - nmB);
                suA += s[mi][ni][0] + s[mi][ni][1];
                suB += s[mi][ni][2] + s[mi][ni][3];
            }
            suA += __shfl_xor_sync(0xffffffffu, suA, 1);
            suA += __shfl_xor_sync(0xffffffffu, suA, 2);
            suB += __shfl_xor_sync(0xffffffffu, suB, 1);
            suB += __shfl_xor_sync(0xffffffffu, suB, 2);
            if (t4 == 0) {
                sWsum[wn * 128 + rA] = suA;
                sWsum[wn * 128 + rB] = suB;
            }
        }
        __syncthreads();

        // ---- owner update of m, l, alpha ----
        if (wn == 0 && t4 == 0) {
#pragma unroll
            for (int mi = 0; mi < 2; mi++)
#pragma unroll
                for (int half = 0; half < 2; half++) {
                    int r = 32 * wm + 16 * mi + half * 8 + g;
                    float om = sM[r];
                    float nm = fmaxf(om, fmaxf(sWmax[r], sWmax[128 + r]));
                    float a  = __expf(om - nm);
                    sL[r]   = a * sL[r] + sWsum[r] + sWsum[128 + r];
                    sM[r]   = nm;
                    sAl_[r] = a;
                }
        }
        __syncthreads();

        // ---- rescale O, then O += P @ V ----
#pragma unroll
        for (int mi = 0; mi < 2; mi++) {
            int rA = 32 * wm + 16 * mi + g;
            float aA = sAl_[rA], aB = sAl_[rA + 8];
#pragma unroll
            for (int ni = 0; ni < 8; ni++) {
                o[mi][ni][0] *= aA; o[mi][ni][1] *= aA;
                o[mi][ni][2] *= aB; o[mi][ni][3] *= aB;
            }
        }
#pragma unroll
        for (int kk2 = 0; kk2 < 4; kk2++) {
            uint32_t aH[2][4], aL[2][4];
#pragma unroll
            for (int mi = 0; mi < 2; mi++) {
                split2(s[mi][2 * kk2][0],     s[mi][2 * kk2][1],     aH[mi][0], aL[mi][0]);
                split2(s[mi][2 * kk2][2],     s[mi][2 * kk2][3],     aH[mi][1], aL[mi][1]);
                split2(s[mi][2 * kk2 + 1][0], s[mi][2 * kk2 + 1][1], aH[mi][2], aL[mi][2]);
                split2(s[mi][2 * kk2 + 1][2], s[mi][2 * kk2 + 1][3], aH[mi][3], aL[mi][3]);
            }
            const int vrw = 64 * wn + 16 * kk2 + (lane & 7) + ((lane >> 3) & 1) * 8;
#pragma unroll
            for (int nn = 0; nn < 4; nn++) {
                const int vch = 2 * nn + (lane >> 4);
                uint32_t off = swzF(vrw, vch);
                uint32_t bh[4], bl[4];
                ldm_x4_t(bh, st + 32768u + off);
                ldm_x4_t(bl, st + 49152u + off);
#pragma unroll
                for (int sub = 0; sub < 2; sub++) {
                    const int ni = 2 * nn + sub;
#pragma unroll
                    for (int mi = 0; mi < 2; mi++) {
                        mma16816(o[mi][ni], aH[mi], bh + 2 * sub);
                        mma16816(o[mi][ni], aH[mi], bl + 2 * sub);
                        mma16816(o[mi][ni], aL[mi], bh + 2 * sub);
                    }
                }
            }
        }
        __syncthreads();   // guards stage overwrite by next issue
    }

    // ---- cross-warp (wn) reduction + normalize + split store ----
    float* sO = (float*)(sm_);   // reuse Q region (32KB = 128*64 fp32)
    if (wn == 1) {
#pragma unroll
        for (int mi = 0; mi < 2; mi++) {
            int rA = 32 * wm + 16 * mi + g;
#pragma unroll
            for (int ni = 0; ni < 8; ni++) {
                int d = 8 * ni + 2 * t4;
                sO[rA * 64 + d]       = o[mi][ni][0];
                sO[rA * 64 + d + 1]   = o[mi][ni][1];
                sO[(rA + 8) * 64 + d]     = o[mi][ni][2];
                sO[(rA + 8) * 64 + d + 1] = o[mi][ni][3];
            }
        }
    }
    __syncthreads();
    if (wn == 0) {
#pragma unroll
        for (int mi = 0; mi < 2; mi++) {
            int rA = 32 * wm + 16 * mi + g;
            int rB = rA + 8;
            float iA = 1.f / sL[rA];
            float iB = 1.f / sL[rB];
#pragma unroll
            for (int ni = 0; ni < 8; ni++) {
                int d = 8 * ni + 2 * t4;
                float v0 = (o[mi][ni][0] + sO[rA * 64 + d]) * iA;
                float v1 = (o[mi][ni][1] + sO[rA * 64 + d + 1]) * iA;
                float v2 = (o[mi][ni][2] + sO[rB * 64 + d]) * iB;
                float v3 = (o[mi][ni][3] + sO[rB * 64 + d + 1]) * iB;
                uint32_t hh, ll;
                split2(v0, v1, hh, ll);
                *reinterpret_cast<uint32_t*>(atth + (qrow0 + rA) * INNER_ + h * 64 + d) = hh;
                *reinterpret_cast<uint32_t*>(attl + (qrow0 + rA) * INNER_ + h * 64 + d) = ll;
                split2(v2, v3, hh, ll);
                *reinterpret_cast<uint32_t*>(atth + (qrow0 + rB) * INNER_ + h * 64 + d) = hh;
                *reinterpret_cast<uint32_t*>(attl + (qrow0 + rB) * INNER_ + h * 64 + d) = ll;
            }
        }
    }
}

// ---------------------------------------------------------------------------
extern "C" void kernel_launch(void* const* d_in, const int* /*in_sizes*/,
                              int /*n_in*/, void* d_out, int /*out_size*/) {
    const float* x   = (const float*)d_in[0];
    const float* g   = (const float*)d_in[1];
    const float* wq  = (const float*)d_in[2];
    const float* wkv = (const float*)d_in[3];
    const float* wo  = (const float*)d_in[4];
    float* out = (float*)d_out;

    __nv_bfloat16 *xnh, *xnl, *qkvh, *qkvl, *atth, *attl, *wqkvh, *wqkvl, *woh, *wol;
    cudaGetSymbolAddress((void**)&xnh,   g_xnh);
    cudaGetSymbolAddress((void**)&xnl,   g_xnl);
    cudaGetSymbolAddress((void**)&qkvh,  g_qkvh);
    cudaGetSymbolAddress((void**)&qkvl,  g_qkvl);
    cudaGetSymbolAddress((void**)&atth,  g_atth);
    cudaGetSymbolAddress((void**)&attl,  g_attl);
    cudaGetSymbolAddress((void**)&wqkvh, g_wqkvh);
    cudaGetSymbolAddress((void**)&wqkvl, g_wqkvl);
    cudaGetSymbolAddress((void**)&woh,   g_woh);
    cudaGetSymbolAddress((void**)&wol,   g_wol);

    cudaFuncSetAttribute(gemm_tc<true>,
                         cudaFuncAttributeMaxDynamicSharedMemorySize, 65536);
    cudaFuncSetAttribute(gemm_tc<false>,
                         cudaFuncAttributeMaxDynamicSharedMemorySize, 65536);
    cudaFuncSetAttribute(flash_kernel,
                         cudaFuncAttributeMaxDynamicSharedMemorySize, FLASH_SMEM);

    // LayerNorm (sequence-axis stats) -> split bf16
    ln_partial_kernel<<<dim3(DIM_ / 256, NCHUNK_, B_), 256>>>(x);
    ln_stats_kernel<<<dim3(DIM_ / 256, 1, B_), 256>>>(g);
    ln_norm_kernel<<<(B_ * N_ * DIM_ / 4) / 256, 256>>>(x);

    // weight conversion (q scale folded)
    conv_qkv_kernel<<<(DIM_ * QKVN_ / 4) / 256, 256>>>(wq, wkv);
    conv_wo_kernel<<<(INNER_ * DIM_ / 4) / 256, 256>>>(wo);

    // fused qkv projection: [4096 x 1536]
    gemm_tc<true><<<dim3(QKVN_ / 128, (B_ * N_) / 128), 256, 65536>>>(
        xnh, xnl, wqkvh, wqkvl, nullptr, qkvh, qkvl, DIM_, QKVN_);

    // fused attention
    flash_kernel<<<dim3(N_ / 128, HEADS_, B_), 256, FLASH_SMEM>>>(
        qkvh, qkvl, atth, attl);

    // output projection: [4096 x 1024]
    gemm_tc<false><<<dim3(DIM_ / 128, (B_ * N_) / 128), 256, 65536>>>(
        atth, attl, woh, wol, out, nullptr, nullptr, INNER_, DIM_);
}

// round 5
// speedup vs baseline: 4.8273x; 1.3248x over previous
#include <cuda_runtime.h>
#include <cuda_fp16.h>
#include <cstdint>

namespace {
constexpr int B_      = 2;
constexpr int N_      = 2048;
constexpr int DIM_    = 1024;
constexpr int HEADS_  = 8;
constexpr int DHEAD_  = 64;
constexpr int INNER_  = 512;
constexpr int QKVN_   = 1536;   // fused q|k|v columns
constexpr float EPS_  = 1e-5f;
constexpr int NCHUNK_ = 16;
constexpr int CH_     = N_ / NCHUNK_;
}

// Scratch. A-side operands: fp16 hi/lo split. B-side operands: single fp16.
__device__ __half g_xnh [B_ * N_ * DIM_],   g_xnl [B_ * N_ * DIM_];
__device__ __half g_qh  [B_ * N_ * INNER_], g_ql  [B_ * N_ * INNER_];
__device__ __half g_kv16[B_ * N_ * 2 * INNER_];
__device__ __half g_atth[B_ * N_ * INNER_], g_attl[B_ * N_ * INNER_];
__device__ __half g_wqkv16[DIM_ * QKVN_];      // [K][N] row-major
__device__ __half g_wo16  [INNER_ * DIM_];     // [K][N] row-major
__device__ float g_ps [B_ * NCHUNK_ * DIM_];
__device__ float g_pss[B_ * NCHUNK_ * DIM_];
__device__ float g_scale[B_ * DIM_];
__device__ float g_bias [B_ * DIM_];

// ---------------------------------------------------------------------------
// Helpers
// ---------------------------------------------------------------------------
__device__ __forceinline__ void split2h(float x, float y, uint32_t& h, uint32_t& l) {
    __half hx = __float2half_rn(x);
    __half hy = __float2half_rn(y);
    __half lx = __float2half_rn(x - __half2float(hx));
    __half ly = __float2half_rn(y - __half2float(hy));
    __half2 hp = __halves2half2(hx, hy), lp = __halves2half2(lx, ly);
    h = *reinterpret_cast<uint32_t*>(&hp);
    l = *reinterpret_cast<uint32_t*>(&lp);
}
__device__ __forceinline__ uint32_t pack2h(float x, float y) {
    __half2 p = __halves2half2(__float2half_rn(x), __float2half_rn(y));
    return *reinterpret_cast<uint32_t*>(&p);
}

__device__ __forceinline__ void mma16816(float* c, const uint32_t* a, const uint32_t* b) {
    asm volatile(
        "mma.sync.aligned.m16n8k16.row.col.f32.f16.f16.f32 "
        "{%0,%1,%2,%3},{%4,%5,%6,%7},{%8,%9},{%0,%1,%2,%3};\n"
        : "+f"(c[0]), "+f"(c[1]), "+f"(c[2]), "+f"(c[3])
        : "r"(a[0]), "r"(a[1]), "r"(a[2]), "r"(a[3]), "r"(b[0]), "r"(b[1]));
}

__device__ __forceinline__ uint32_t smem_u32(const void* p) {
    return (uint32_t)__cvta_generic_to_shared(p);
}
__device__ __forceinline__ void ldm_x4(uint32_t* r, uint32_t a) {
    asm volatile("ldmatrix.sync.aligned.m8n8.x4.shared.b16 {%0,%1,%2,%3},[%4];"
                 : "=r"(r[0]), "=r"(r[1]), "=r"(r[2]), "=r"(r[3]) : "r"(a));
}
__device__ __forceinline__ void ldm_x4_t(uint32_t* r, uint32_t a) {
    asm volatile("ldmatrix.sync.aligned.m8n8.x4.trans.shared.b16 {%0,%1,%2,%3},[%4];"
                 : "=r"(r[0]), "=r"(r[1]), "=r"(r[2]), "=r"(r[3]) : "r"(a));
}
__device__ __forceinline__ void cp16(uint32_t dst, const void* src) {
    asm volatile("cp.async.cg.shared.global [%0],[%1],16;\n" :: "r"(dst), "l"(src));
}
__device__ __forceinline__ void cp_commit() {
    asm volatile("cp.async.commit_group;\n" ::: "memory");
}
__device__ __forceinline__ void cp_wait1() {
    asm volatile("cp.async.wait_group 1;\n" ::: "memory");
}

// Swizzles (16B chunk granularity)
__device__ __forceinline__ uint32_t swzA(int r, int c) {   // 64B rows, c in [0,4)
    return (uint32_t)(r * 64 + ((c ^ ((r >> 1) & 3)) << 4));
}
__device__ __forceinline__ uint32_t swzB(int r, int c) {   // 256B rows, c in [0,16)
    return (uint32_t)(r * 256 + ((c ^ (r & 7)) << 4));
}
__device__ __forceinline__ uint32_t swzF(int r, int c) {   // 128B rows, c in [0,8)
    return (uint32_t)(r * 128 + ((c ^ (r & 7)) << 4));
}

// ---------------------------------------------------------------------------
// LayerNorm over sequence axis (axis=1)
// ---------------------------------------------------------------------------
__global__ void ln_partial_kernel(const float* __restrict__ x) {
    int d = blockIdx.x * blockDim.x + threadIdx.x;
    int c = blockIdx.y;
    int b = blockIdx.z;
    const float* px = x + ((size_t)b * N_ + (size_t)c * CH_) * DIM_ + d;
    float s = 0.f, ss = 0.f;
#pragma unroll 4
    for (int n = 0; n < CH_; n++) {
        float v = px[(size_t)n * DIM_];
        s += v;
        ss += v * v;
    }
    size_t o = ((size_t)b * NCHUNK_ + c) * DIM_ + d;
    g_ps[o]  = s;
    g_pss[o] = ss;
}

__global__ void ln_stats_kernel(const float* __restrict__ g) {
    int d = blockIdx.x * blockDim.x + threadIdx.x;
    int b = blockIdx.z;
    float s = 0.f, ss = 0.f;
#pragma unroll
    for (int c = 0; c < NCHUNK_; c++) {
        size_t o = ((size_t)b * NCHUNK_ + c) * DIM_ + d;
        s += g_ps[o];
        ss += g_pss[o];
    }
    float mean = s * (1.f / N_);
    float var  = fmaf(-mean, mean, ss * (1.f / N_));
    float sc   = rsqrtf(var + EPS_) * g[d];
    g_scale[b * DIM_ + d] = sc;
    g_bias[b * DIM_ + d]  = -mean * sc;
}

__global__ void ln_norm_kernel(const float* __restrict__ x) {
    int i = blockIdx.x * blockDim.x + threadIdx.x;
    int elem = i * 4;
    int d = elem & (DIM_ - 1);
    int b = elem / (N_ * DIM_);
    float4 xv = reinterpret_cast<const float4*>(x)[i];
    float4 sc = *reinterpret_cast<const float4*>(&g_scale[b * DIM_ + d]);
    float4 bi = *reinterpret_cast<const float4*>(&g_bias[b * DIM_ + d]);
    float rx = fmaf(xv.x, sc.x, bi.x);
    float ry = fmaf(xv.y, sc.y, bi.y);
    float rz = fmaf(xv.z, sc.z, bi.z);
    float rw = fmaf(xv.w, sc.w, bi.w);
    uint32_t h0, l0, h1, l1;
    split2h(rx, ry, h0, l0);
    split2h(rz, rw, h1, l1);
    uint2 hh = {h0, h1}, ll = {l0, l1};
    reinterpret_cast<uint2*>(g_xnh)[i] = hh;
    reinterpret_cast<uint2*>(g_xnl)[i] = ll;
}

// ---------------------------------------------------------------------------
// Weight conversion (single fp16, K-major [K][N]); q scale folded.
// ---------------------------------------------------------------------------
__global__ void conv_qkv16(const float* __restrict__ wq, const float* __restrict__ wkv) {
    int i = blockIdx.x * blockDim.x + threadIdx.x;
    int elem = i * 4;
    int row = elem / QKVN_, col = elem % QKVN_;
    float4 v;
    if (col < INNER_) {
        v = *reinterpret_cast<const float4*>(wq + (size_t)row * INNER_ + col);
        v.x *= 0.125f; v.y *= 0.125f; v.z *= 0.125f; v.w *= 0.125f;
    } else {
        v = *reinterpret_cast<const float4*>(wkv + (size_t)row * (2 * INNER_) + col - INNER_);
    }
    uint2 u = {pack2h(v.x, v.y), pack2h(v.z, v.w)};
    reinterpret_cast<uint2*>(g_wqkv16)[i] = u;
}

__global__ void conv_wo16(const float* __restrict__ wo) {
    int i = blockIdx.x * blockDim.x + threadIdx.x;
    float4 v = reinterpret_cast<const float4*>(wo)[i];
    uint2 u = {pack2h(v.x, v.y), pack2h(v.z, v.w)};
    reinterpret_cast<uint2*>(g_wo16)[i] = u;
}

// ---------------------------------------------------------------------------
// fp16 2-term tensor-core GEMM. C[M,N] = (Ah+Al)[M,K] @ B[K,N].
// 128x128 tile, BK=32, 2-stage cp.async, ldmatrix operands, 2 MMAs/logical.
// Stage (24KB): Ah 0 | Al 8192 | B 16384. MODE 0: fp32 out. MODE 1: qkv
// epilogue (cols<512 -> q hi/lo; cols>=512 -> single fp16 kv).
// ---------------------------------------------------------------------------
template <int MODE>
__global__ void __launch_bounds__(256, 2)
gemm_fp16(const __half* __restrict__ Ah, const __half* __restrict__ Al,
          const __half* __restrict__ B, float* __restrict__ C,
          __half* __restrict__ Qh, __half* __restrict__ Ql,
          __half* __restrict__ KV, int K, int N) {
    extern __shared__ char sm_[];
    const uint32_t sb = smem_u32(sm_);
    const int tid = threadIdx.x, lane = tid & 31, w = tid >> 5;
    const int wm = w >> 1, wn = w & 1, g = lane >> 2, t4 = lane & 3;
    const int row0 = blockIdx.y * 128, col0 = blockIdx.x * 128;
    const int KT = K >> 5;

    const int ar = tid >> 2, ac = tid & 3;
    const int br = tid >> 4, bc = tid & 15;

    auto issue = [&](int kt) {
        const uint32_t st = sb + (uint32_t)(kt & 1) * 24576u;
        const __half* pah = Ah + (size_t)(row0 + ar) * K + kt * 32 + ac * 8;
        const __half* pal = Al + (size_t)(row0 + ar) * K + kt * 32 + ac * 8;
        cp16(st + swzA(ar, ac), pah);
        cp16(st + swzA(ar + 64, ac), pah + (size_t)64 * K);
        cp16(st + 8192u + swzA(ar, ac), pal);
        cp16(st + 8192u + swzA(ar + 64, ac), pal + (size_t)64 * K);
        const __half* pb = B + (size_t)(kt * 32 + br) * N + col0 + bc * 8;
        cp16(st + 16384u + swzB(br, bc), pb);
        cp16(st + 16384u + swzB(br + 16, bc), pb + (size_t)16 * N);
        cp_commit();
    };

    float acc[2][8][4];
#pragma unroll
    for (int mi = 0; mi < 2; mi++)
#pragma unroll
        for (int ni = 0; ni < 8; ni++)
#pragma unroll
            for (int j = 0; j < 4; j++) acc[mi][ni][j] = 0.f;

    issue(0);
    for (int kt = 0; kt < KT; kt++) {
        if (kt + 1 < KT) issue(kt + 1);
        else cp_commit();
        cp_wait1();
        __syncthreads();
        const uint32_t st = sb + (uint32_t)(kt & 1) * 24576u;
#pragma unroll
        for (int kk = 0; kk < 2; kk++) {
            uint32_t aH[2][4], aL[2][4];
            const int arow = 32 * wm + (lane & 15);
            const int ach  = 2 * kk + (lane >> 4);
#pragma unroll
            for (int mi = 0; mi < 2; mi++) {
                uint32_t off = swzA(arow + 16 * mi, ach);
                ldm_x4(aH[mi], st + off);
                ldm_x4(aL[mi], st + 8192u + off);
            }
            const int brow = 16 * kk + (lane & 7) + ((lane >> 3) & 1) * 8;
#pragma unroll
            for (int nn = 0; nn < 4; nn++) {
                const int bch = 8 * wn + 2 * nn + (lane >> 4);
                uint32_t bh[4];
                ldm_x4_t(bh, st + 16384u + swzB(brow, bch));
#pragma unroll
                for (int sub = 0; sub < 2; sub++) {
                    const int ni = 2 * nn + sub;
#pragma unroll
                    for (int mi = 0; mi < 2; mi++) {
                        mma16816(acc[mi][ni], aH[mi], bh + 2 * sub);
                        mma16816(acc[mi][ni], aL[mi], bh + 2 * sub);
                    }
                }
            }
        }
        __syncthreads();
    }

#pragma unroll
    for (int mi = 0; mi < 2; mi++) {
        int rA = row0 + 32 * wm + 16 * mi + g;
#pragma unroll
        for (int ni = 0; ni < 8; ni++) {
            int col = col0 + 64 * wn + 8 * ni + 2 * t4;
            if (MODE == 0) {
                float2 v0 = {acc[mi][ni][0], acc[mi][ni][1]};
                float2 v1 = {acc[mi][ni][2], acc[mi][ni][3]};
                *reinterpret_cast<float2*>(C + (size_t)rA * N + col) = v0;
                *reinterpret_cast<float2*>(C + (size_t)(rA + 8) * N + col) = v1;
            } else {
                if (col0 < INNER_) {   // q region: split hi/lo
                    uint32_t h, l;
                    split2h(acc[mi][ni][0], acc[mi][ni][1], h, l);
                    *reinterpret_cast<uint32_t*>(Qh + (size_t)rA * INNER_ + col) = h;
                    *reinterpret_cast<uint32_t*>(Ql + (size_t)rA * INNER_ + col) = l;
                    split2h(acc[mi][ni][2], acc[mi][ni][3], h, l);
                    *reinterpret_cast<uint32_t*>(Qh + (size_t)(rA + 8) * INNER_ + col) = h;
                    *reinterpret_cast<uint32_t*>(Ql + (size_t)(rA + 8) * INNER_ + col) = l;
                } else {               // kv region: single fp16
                    int ck = col - INNER_;
                    *reinterpret_cast<uint32_t*>(KV + (size_t)rA * (2 * INNER_) + ck) =
                        pack2h(acc[mi][ni][0], acc[mi][ni][1]);
                    *reinterpret_cast<uint32_t*>(KV + (size_t)(rA + 8) * (2 * INNER_) + ck) =
                        pack2h(acc[mi][ni][2], acc[mi][ni][3]);
                }
            }
        }
    }
}

// ---------------------------------------------------------------------------
// Flash attention: Q hi/lo (staged once), K/V single fp16 double-buffered.
// 2 MMAs per logical. P in registers (fp16 hi/lo at use time).
// Smem: Qh 0 (16K) | Ql 16384 | stages at 32768 + s*32768 {K 0 | V 16384}
//       stats at 98304. Total 101888.
// ---------------------------------------------------------------------------
namespace { constexpr int FLASH_SMEM = 101888; }

__global__ void __launch_bounds__(256)
flash_kernel(const __half* __restrict__ qh, const __half* __restrict__ ql,
             const __half* __restrict__ kv,
             __half* __restrict__ atth, __half* __restrict__ attl) {
    extern __shared__ char sm_[];
    const uint32_t sb = smem_u32(sm_);
    float* sM    = (float*)(sm_ + 98304);
    float* sL    = sM + 128;
    float* sAl_  = sM + 256;
    float* sWmax = sM + 384;   // [2][128]
    float* sWsum = sM + 640;   // [2][128]

    const int tid = threadIdx.x, lane = tid & 31, w = tid >> 5;
    const int wm = w >> 1, wn = w & 1, g = lane >> 2, t4 = lane & 3;
    const int qt = blockIdx.x, h = blockIdx.y, b = blockIdx.z;
    const size_t qrow0 = (size_t)(b * N_ + qt * 128);

    if (tid < 128) { sM[tid] = -1e30f; sL[tid] = 0.f; }

    // stage Q hi/lo (with KV stage 0's group)
    {
        int r = tid >> 3, c = tid & 7;
        const __half* ph = qh + (qrow0 + r) * INNER_ + h * 64 + c * 8;
        const __half* pl = ql + (qrow0 + r) * INNER_ + h * 64 + c * 8;
#pragma unroll
        for (int it = 0; it < 4; it++) {
            uint32_t o = swzF(r + 32 * it, c);
            size_t go = (size_t)(32 * it) * INNER_;
            cp16(sb + o, ph + go);
            cp16(sb + 16384u + o, pl + go);
        }
    }

    auto issueKV = [&](int kt) {
        const uint32_t st = sb + 32768u + (uint32_t)(kt & 1) * 32768u;
        int r = tid >> 3, c = tid & 7;
        size_t rowb = (size_t)(b * N_ + kt * 128);
        const __half* pk = kv + (rowb + r) * (2 * INNER_) + h * 64 + c * 8;
#pragma unroll
        for (int it = 0; it < 4; it++) {
            uint32_t o = swzF(r + 32 * it, c);
            size_t go = (size_t)(32 * it) * (2 * INNER_);
            cp16(st + o,           pk + go);
            cp16(st + 16384u + o,  pk + go + 512);   // V = K + 512 cols
        }
        cp_commit();
    };

    issueKV(0);

    float o[2][8][4];
#pragma unroll
    for (int mi = 0; mi < 2; mi++)
#pragma unroll
        for (int ni = 0; ni < 8; ni++)
#pragma unroll
            for (int j = 0; j < 4; j++) o[mi][ni][j] = 0.f;

    for (int kt = 0; kt < 16; kt++) {
        if (kt + 1 < 16) issueKV(kt + 1);
        else cp_commit();
        cp_wait1();
        __syncthreads();
        const uint32_t st = sb + 32768u + (uint32_t)(kt & 1) * 32768u;

        // ---- S = Q K^T ----
        float s[2][8][4];
#pragma unroll
        for (int mi = 0; mi < 2; mi++)
#pragma unroll
            for (int ni = 0; ni < 8; ni++)
#pragma unroll
                for (int j = 0; j < 4; j++) s[mi][ni][j] = 0.f;

#pragma unroll
        for (int kk = 0; kk < 4; kk++) {
            uint32_t aH[2][4], aL[2][4];
            const int arow = 32 * wm + (lane & 15);
            const int ach  = 2 * kk + (lane >> 4);
#pragma unroll
            for (int mi = 0; mi < 2; mi++) {
                uint32_t off = swzF(arow + 16 * mi, ach);
                ldm_x4(aH[mi], sb + off);
                ldm_x4(aL[mi], sb + 16384u + off);
            }
            const int krw = (lane & 7) + (lane >> 4) * 8;
            const int kch = 2 * kk + ((lane >> 3) & 1);
#pragma unroll
            for (int nn = 0; nn < 4; nn++) {
                uint32_t bh[4];
                ldm_x4(bh, st + swzF(64 * wn + 16 * nn + krw, kch));
#pragma unroll
                for (int sub = 0; sub < 2; sub++) {
                    const int ni = 2 * nn + sub;
#pragma unroll
                    for (int mi = 0; mi < 2; mi++) {
                        mma16816(s[mi][ni], aH[mi], bh + 2 * sub);
                        mma16816(s[mi][ni], aL[mi], bh + 2 * sub);
                    }
                }
            }
        }

        // ---- row max ----
#pragma unroll
        for (int mi = 0; mi < 2; mi++) {
            float ma = -1e30f, mb = -1e30f;
#pragma unroll
            for (int ni = 0; ni < 8; ni++) {
                ma = fmaxf(ma, fmaxf(s[mi][ni][0], s[mi][ni][1]));
                mb = fmaxf(mb, fmaxf(s[mi][ni][2], s[mi][ni][3]));
            }
            ma = fmaxf(ma, __shfl_xor_sync(0xffffffffu, ma, 1));
            ma = fmaxf(ma, __shfl_xor_sync(0xffffffffu, ma, 2));
            mb = fmaxf(mb, __shfl_xor_sync(0xffffffffu, mb, 1));
            mb = fmaxf(mb, __shfl_xor_sync(0xffffffffu, mb, 2));
            if (t4 == 0) {
                int rA = 32 * wm + 16 * mi + g;
                sWmax[wn * 128 + rA]     = ma;
                sWmax[wn * 128 + rA + 8] = mb;
            }
        }
        __syncthreads();

        // ---- exp + partial sums ----
#pragma unroll
        for (int mi = 0; mi < 2; mi++) {
            int rA = 32 * wm + 16 * mi + g;
            int rB = rA + 8;
            float nmA = fmaxf(sM[rA], fmaxf(sWmax[rA], sWmax[128 + rA]));
            float nmB = fmaxf(sM[rB], fmaxf(sWmax[rB], sWmax[128 + rB]));
            float suA = 0.f, suB = 0.f;
#pragma unroll
            for (int ni = 0; ni < 8; ni++) {
                s[mi][ni][0] = __expf(s[mi][ni][0] - nmA);
                s[mi][ni][1] = __expf(s[mi][ni][1] - nmA);
                s[mi][ni][2] = __expf(s[mi][ni][2] - nmB);
                s[mi][ni][3] = __expf(s[mi][ni][3] - nmB);
                suA += s[mi][ni][0] + s[mi][ni][1];
                suB += s[mi][ni][2] + s[mi][ni][3];
            }
            suA += __shfl_xor_sync(0xffffffffu, suA, 1);
            suA += __shfl_xor_sync(0xffffffffu, suA, 2);
            suB += __shfl_xor_sync(0xffffffffu, suB, 1);
            suB += __shfl_xor_sync(0xffffffffu, suB, 2);
            if (t4 == 0) {
                sWsum[wn * 128 + rA] = suA;
                sWsum[wn * 128 + rB] = suB;
            }
        }
        __syncthreads();

        // ---- owner update ----
        if (wn == 0 && t4 == 0) {
#pragma unroll
            for (int mi = 0; mi < 2; mi++)
#pragma unroll
                for (int half = 0; half < 2; half++) {
                    int rr = 32 * wm + 16 * mi + half * 8 + g;
                    float om = sM[rr];
                    float nm = fmaxf(om, fmaxf(sWmax[rr], sWmax[128 + rr]));
                    float a  = __expf(om - nm);
                    sL[rr]   = a * sL[rr] + sWsum[rr] + sWsum[128 + rr];
                    sM[rr]   = nm;
                    sAl_[rr] = a;
                }
        }
        __syncthreads();

        // ---- rescale O, O += P @ V ----
#pragma unroll
        for (int mi = 0; mi < 2; mi++) {
            int rA = 32 * wm + 16 * mi + g;
            float aA = sAl_[rA], aB = sAl_[rA + 8];
#pragma unroll
            for (int ni = 0; ni < 8; ni++) {
                o[mi][ni][0] *= aA; o[mi][ni][1] *= aA;
                o[mi][ni][2] *= aB; o[mi][ni][3] *= aB;
            }
        }
#pragma unroll
        for (int kk2 = 0; kk2 < 4; kk2++) {
            uint32_t aH[2][4], aL[2][4];
#pragma unroll
            for (int mi = 0; mi < 2; mi++) {
                split2h(s[mi][2 * kk2][0],     s[mi][2 * kk2][1],     aH[mi][0], aL[mi][0]);
                split2h(s[mi][2 * kk2][2],     s[mi][2 * kk2][3],     aH[mi][1], aL[mi][1]);
                split2h(s[mi][2 * kk2 + 1][0], s[mi][2 * kk2 + 1][1], aH[mi][2], aL[mi][2]);
                split2h(s[mi][2 * kk2 + 1][2], s[mi][2 * kk2 + 1][3], aH[mi][3], aL[mi][3]);
            }
            const int vrw = 64 * wn + 16 * kk2 + (lane & 7) + ((lane >> 3) & 1) * 8;
#pragma unroll
            for (int nn = 0; nn < 4; nn++) {
                const int vch = 2 * nn + (lane >> 4);
                uint32_t bh[4];
                ldm_x4_t(bh, st + 16384u + swzF(vrw, vch));
#pragma unroll
                for (int sub = 0; sub < 2; sub++) {
                    const int ni = 2 * nn + sub;
#pragma unroll
                    for (int mi = 0; mi < 2; mi++) {
                        mma16816(o[mi][ni], aH[mi], bh + 2 * sub);
                        mma16816(o[mi][ni], aL[mi], bh + 2 * sub);
                    }
                }
            }
        }
        __syncthreads();
    }

    // ---- cross-warp reduction + normalize + split store ----
    float* sO = (float*)(sm_);   // reuse Q region (32KB)
    if (wn == 1) {
#pragma unroll
        for (int mi = 0; mi < 2; mi++) {
            int rA = 32 * wm + 16 * mi + g;
#pragma unroll
            for (int ni = 0; ni < 8; ni++) {
                int d = 8 * ni + 2 * t4;
                sO[rA * 64 + d]           = o[mi][ni][0];
                sO[rA * 64 + d + 1]       = o[mi][ni][1];
                sO[(rA + 8) * 64 + d]     = o[mi][ni][2];
                sO[(rA + 8) * 64 + d + 1] = o[mi][ni][3];
            }
        }
    }
    __syncthreads();
    if (wn == 0) {
#pragma unroll
        for (int mi = 0; mi < 2; mi++) {
            int rA = 32 * wm + 16 * mi + g;
            int rB = rA + 8;
            float iA = 1.f / sL[rA];
            float iB = 1.f / sL[rB];
#pragma unroll
            for (int ni = 0; ni < 8; ni++) {
                int d = 8 * ni + 2 * t4;
                float v0 = (o[mi][ni][0] + sO[rA * 64 + d]) * iA;
                float v1 = (o[mi][ni][1] + sO[rA * 64 + d + 1]) * iA;
                float v2 = (o[mi][ni][2] + sO[rB * 64 + d]) * iB;
                float v3 = (o[mi][ni][3] + sO[rB * 64 + d + 1]) * iB;
                uint32_t hh, ll;
                split2h(v0, v1, hh, ll);
                *reinterpret_cast<uint32_t*>(atth + (qrow0 + rA) * INNER_ + h * 64 + d) = hh;
                *reinterpret_cast<uint32_t*>(attl + (qrow0 + rA) * INNER_ + h * 64 + d) = ll;
                split2h(v2, v3, hh, ll);
                *reinterpret_cast<uint32_t*>(atth + (qrow0 + rB) * INNER_ + h * 64 + d) = hh;
                *reinterpret_cast<uint32_t*>(attl + (qrow0 + rB) * INNER_ + h * 64 + d) = ll;
            }
        }
    }
}

// ---------------------------------------------------------------------------
extern "C" void kernel_launch(void* const* d_in, const int* /*in_sizes*/,
                              int /*n_in*/, void* d_out, int /*out_size*/) {
    const float* x   = (const float*)d_in[0];
    const float* g   = (const float*)d_in[1];
    const float* wq  = (const float*)d_in[2];
    const float* wkv = (const float*)d_in[3];
    const float* wo  = (const float*)d_in[4];
    float* out = (float*)d_out;

    __half *xnh, *xnl, *qh, *ql, *kv, *atth, *attl, *wqkv, *wo16;
    cudaGetSymbolAddress((void**)&xnh,  g_xnh);
    cudaGetSymbolAddress((void**)&xnl,  g_xnl);
    cudaGetSymbolAddress((void**)&qh,   g_qh);
    cudaGetSymbolAddress((void**)&ql,   g_ql);
    cudaGetSymbolAddress((void**)&kv,   g_kv16);
    cudaGetSymbolAddress((void**)&atth, g_atth);
    cudaGetSymbolAddress((void**)&attl, g_attl);
    cudaGetSymbolAddress((void**)&wqkv, g_wqkv16);
    cudaGetSymbolAddress((void**)&wo16, g_wo16);

    cudaFuncSetAttribute(gemm_fp16<0>,
                         cudaFuncAttributeMaxDynamicSharedMemorySize, 49152);
    cudaFuncSetAttribute(gemm_fp16<1>,
                         cudaFuncAttributeMaxDynamicSharedMemorySize, 49152);
    cudaFuncSetAttribute(flash_kernel,
                         cudaFuncAttributeMaxDynamicSharedMemorySize, FLASH_SMEM);

    // LayerNorm (sequence-axis stats) -> fp16 hi/lo
    ln_partial_kernel<<<dim3(DIM_ / 256, NCHUNK_, B_), 256>>>(x);
    ln_stats_kernel<<<dim3(DIM_ / 256, 1, B_), 256>>>(g);
    ln_norm_kernel<<<(B_ * N_ * DIM_ / 4) / 256, 256>>>(x);

    // weight conversion (single fp16, q scale folded)
    conv_qkv16<<<(DIM_ * QKVN_ / 4) / 256, 256>>>(wq, wkv);
    conv_wo16<<<(INNER_ * DIM_ / 4) / 256, 256>>>(wo);

    // fused qkv projection: [4096 x 1536]
    gemm_fp16<1><<<dim3(QKVN_ / 128, (B_ * N_) / 128), 256, 49152>>>(
        xnh, xnl, wqkv, nullptr, qh, ql, kv, DIM_, QKVN_);

    // fused attention
    flash_kernel<<<dim3(N_ / 128, HEADS_, B_), 256, FLASH_SMEM>>>(
        qh, ql, kv, atth, attl);

    // output projection: [4096 x 1024]
    gemm_fp16<0><<<dim3(DIM_ / 128, (B_ * N_) / 128), 256, 49152>>>(
        atth, attl, wo16, out, nullptr, nullptr, nullptr, INNER_, DIM_);
}

// round 6
// speedup vs baseline: 5.2731x; 1.0923x over previous
#include <cuda_runtime.h>
#include <cuda_fp16.h>
#include <cstdint>

namespace {
constexpr int B_      = 2;
constexpr int N_      = 2048;
constexpr int DIM_    = 1024;
constexpr int HEADS_  = 8;
constexpr int DHEAD_  = 64;
constexpr int INNER_  = 512;
constexpr int QKVN_   = 1536;
constexpr float EPS_  = 1e-5f;
constexpr int NCHUNK_ = 16;
constexpr int CH_     = N_ / NCHUNK_;
}

// Scratch. A-side operands: fp16 hi/lo split. B-side operands: single fp16.
__device__ __half g_xnh [B_ * N_ * DIM_],   g_xnl [B_ * N_ * DIM_];
__device__ __half g_qh  [B_ * N_ * INNER_], g_ql  [B_ * N_ * INNER_];
__device__ __half g_kv16[B_ * N_ * 2 * INNER_];
__device__ __half g_atth[B_ * N_ * INNER_], g_attl[B_ * N_ * INNER_];
__device__ __half g_wqkv16[DIM_ * QKVN_];
__device__ __half g_wo16  [INNER_ * DIM_];
__device__ float g_ps [B_ * NCHUNK_ * DIM_];
__device__ float g_pss[B_ * NCHUNK_ * DIM_];
__device__ float g_scale[B_ * DIM_];
__device__ float g_bias [B_ * DIM_];

// ---------------------------------------------------------------------------
// Helpers
// ---------------------------------------------------------------------------
__device__ __forceinline__ void split2h(float x, float y, uint32_t& h, uint32_t& l) {
    __half hx = __float2half_rn(x);
    __half hy = __float2half_rn(y);
    __half lx = __float2half_rn(x - __half2float(hx));
    __half ly = __float2half_rn(y - __half2float(hy));
    __half2 hp = __halves2half2(hx, hy), lp = __halves2half2(lx, ly);
    h = *reinterpret_cast<uint32_t*>(&hp);
    l = *reinterpret_cast<uint32_t*>(&lp);
}
__device__ __forceinline__ uint32_t pack2h(float x, float y) {
    __half2 p = __halves2half2(__float2half_rn(x), __float2half_rn(y));
    return *reinterpret_cast<uint32_t*>(&p);
}

__device__ __forceinline__ void mma16816(float* c, const uint32_t* a, const uint32_t* b) {
    asm volatile(
        "mma.sync.aligned.m16n8k16.row.col.f32.f16.f16.f32 "
        "{%0,%1,%2,%3},{%4,%5,%6,%7},{%8,%9},{%0,%1,%2,%3};\n"
        : "+f"(c[0]), "+f"(c[1]), "+f"(c[2]), "+f"(c[3])
        : "r"(a[0]), "r"(a[1]), "r"(a[2]), "r"(a[3]), "r"(b[0]), "r"(b[1]));
}

__device__ __forceinline__ uint32_t smem_u32(const void* p) {
    return (uint32_t)__cvta_generic_to_shared(p);
}
__device__ __forceinline__ void ldm_x4(uint32_t* r, uint32_t a) {
    asm volatile("ldmatrix.sync.aligned.m8n8.x4.shared.b16 {%0,%1,%2,%3},[%4];"
                 : "=r"(r[0]), "=r"(r[1]), "=r"(r[2]), "=r"(r[3]) : "r"(a));
}
__device__ __forceinline__ void ldm_x4_t(uint32_t* r, uint32_t a) {
    asm volatile("ldmatrix.sync.aligned.m8n8.x4.trans.shared.b16 {%0,%1,%2,%3},[%4];"
                 : "=r"(r[0]), "=r"(r[1]), "=r"(r[2]), "=r"(r[3]) : "r"(a));
}
__device__ __forceinline__ void cp16(uint32_t dst, const void* src) {
    asm volatile("cp.async.cg.shared.global [%0],[%1],16;\n" :: "r"(dst), "l"(src));
}
__device__ __forceinline__ void cp_commit() {
    asm volatile("cp.async.commit_group;\n" ::: "memory");
}
__device__ __forceinline__ void cp_wait1() {
    asm volatile("cp.async.wait_group 1;\n" ::: "memory");
}

// Swizzles (16B chunk granularity)
__device__ __forceinline__ uint32_t swzA(int r, int c) {   // 64B rows
    return (uint32_t)(r * 64 + ((c ^ ((r >> 1) & 3)) << 4));
}
__device__ __forceinline__ uint32_t swzB(int r, int c) {   // 256B rows
    return (uint32_t)(r * 256 + ((c ^ (r & 7)) << 4));
}
__device__ __forceinline__ uint32_t swzF(int r, int c) {   // 128B rows
    return (uint32_t)(r * 128 + ((c ^ (r & 7)) << 4));
}

// ---------------------------------------------------------------------------
// LayerNorm over sequence axis (axis=1)
// ---------------------------------------------------------------------------
__global__ void ln_partial_kernel(const float* __restrict__ x) {
    int d = blockIdx.x * blockDim.x + threadIdx.x;
    int c = blockIdx.y;
    int b = blockIdx.z;
    const float* px = x + ((size_t)b * N_ + (size_t)c * CH_) * DIM_ + d;
    float s = 0.f, ss = 0.f;
#pragma unroll 4
    for (int n = 0; n < CH_; n++) {
        float v = px[(size_t)n * DIM_];
        s += v;
        ss += v * v;
    }
    size_t o = ((size_t)b * NCHUNK_ + c) * DIM_ + d;
    g_ps[o]  = s;
    g_pss[o] = ss;
}

__global__ void ln_stats_kernel(const float* __restrict__ g) {
    int d = blockIdx.x * blockDim.x + threadIdx.x;
    int b = blockIdx.z;
    float s = 0.f, ss = 0.f;
#pragma unroll
    for (int c = 0; c < NCHUNK_; c++) {
        size_t o = ((size_t)b * NCHUNK_ + c) * DIM_ + d;
        s += g_ps[o];
        ss += g_pss[o];
    }
    float mean = s * (1.f / N_);
    float var  = fmaf(-mean, mean, ss * (1.f / N_));
    float sc   = rsqrtf(var + EPS_) * g[d];
    g_scale[b * DIM_ + d] = sc;
    g_bias[b * DIM_ + d]  = -mean * sc;
}

__global__ void ln_norm_kernel(const float* __restrict__ x) {
    int i = blockIdx.x * blockDim.x + threadIdx.x;
    int elem = i * 4;
    int d = elem & (DIM_ - 1);
    int b = elem / (N_ * DIM_);
    float4 xv = reinterpret_cast<const float4*>(x)[i];
    float4 sc = *reinterpret_cast<const float4*>(&g_scale[b * DIM_ + d]);
    float4 bi = *reinterpret_cast<const float4*>(&g_bias[b * DIM_ + d]);
    float rx = fmaf(xv.x, sc.x, bi.x);
    float ry = fmaf(xv.y, sc.y, bi.y);
    float rz = fmaf(xv.z, sc.z, bi.z);
    float rw = fmaf(xv.w, sc.w, bi.w);
    uint32_t h0, l0, h1, l1;
    split2h(rx, ry, h0, l0);
    split2h(rz, rw, h1, l1);
    uint2 hh = {h0, h1}, ll = {l0, l1};
    reinterpret_cast<uint2*>(g_xnh)[i] = hh;
    reinterpret_cast<uint2*>(g_xnl)[i] = ll;
}

// ---------------------------------------------------------------------------
// Weight conversion (single fp16, K-major [K][N]); q scale folded.
// ---------------------------------------------------------------------------
__global__ void conv_qkv16(const float* __restrict__ wq, const float* __restrict__ wkv) {
    int i = blockIdx.x * blockDim.x + threadIdx.x;
    int elem = i * 4;
    int row = elem / QKVN_, col = elem % QKVN_;
    float4 v;
    if (col < INNER_) {
        v = *reinterpret_cast<const float4*>(wq + (size_t)row * INNER_ + col);
        v.x *= 0.125f; v.y *= 0.125f; v.z *= 0.125f; v.w *= 0.125f;
    } else {
        v = *reinterpret_cast<const float4*>(wkv + (size_t)row * (2 * INNER_) + col - INNER_);
    }
    uint2 u = {pack2h(v.x, v.y), pack2h(v.z, v.w)};
    reinterpret_cast<uint2*>(g_wqkv16)[i] = u;
}

__global__ void conv_wo16(const float* __restrict__ wo) {
    int i = blockIdx.x * blockDim.x + threadIdx.x;
    float4 v = reinterpret_cast<const float4*>(wo)[i];
    uint2 u = {pack2h(v.x, v.y), pack2h(v.z, v.w)};
    reinterpret_cast<uint2*>(g_wo16)[i] = u;
}

// ---------------------------------------------------------------------------
// fp16 2-term tensor-core GEMM, 3-stage cp.async (one sync per chunk).
// Stage (24KB): Ah 0 | Al 8192 | B 16384. 3 stages = 72KB.
// ---------------------------------------------------------------------------
namespace { constexpr int GEMM_SMEM = 3 * 24576; }

template <int MODE>
__global__ void __launch_bounds__(256, 2)
gemm_fp16(const __half* __restrict__ Ah, const __half* __restrict__ Al,
          const __half* __restrict__ B, float* __restrict__ C,
          __half* __restrict__ Qh, __half* __restrict__ Ql,
          __half* __restrict__ KV, int K, int N) {
    extern __shared__ char sm_[];
    const uint32_t sb = smem_u32(sm_);
    const int tid = threadIdx.x, lane = tid & 31, w = tid >> 5;
    const int wm = w >> 1, wn = w & 1, g = lane >> 2, t4 = lane & 3;
    const int row0 = blockIdx.y * 128, col0 = blockIdx.x * 128;
    const int KT = K >> 5;

    const int ar = tid >> 2, ac = tid & 3;
    const int br = tid >> 4, bc = tid & 15;

    auto issue = [&](int kt) {
        const uint32_t st = sb + (uint32_t)(kt % 3) * 24576u;
        const __half* pah = Ah + (size_t)(row0 + ar) * K + kt * 32 + ac * 8;
        const __half* pal = Al + (size_t)(row0 + ar) * K + kt * 32 + ac * 8;
        cp16(st + swzA(ar, ac), pah);
        cp16(st + swzA(ar + 64, ac), pah + (size_t)64 * K);
        cp16(st + 8192u + swzA(ar, ac), pal);
        cp16(st + 8192u + swzA(ar + 64, ac), pal + (size_t)64 * K);
        const __half* pb = B + (size_t)(kt * 32 + br) * N + col0 + bc * 8;
        cp16(st + 16384u + swzB(br, bc), pb);
        cp16(st + 16384u + swzB(br + 16, bc), pb + (size_t)16 * N);
        cp_commit();
    };

    float acc[2][8][4];
#pragma unroll
    for (int mi = 0; mi < 2; mi++)
#pragma unroll
        for (int ni = 0; ni < 8; ni++)
#pragma unroll
            for (int j = 0; j < 4; j++) acc[mi][ni][j] = 0.f;

    issue(0);
    issue(1);
    for (int kt = 0; kt < KT; kt++) {
        cp_wait1();          // stage kt done (kt+1 may be in flight)
        __syncthreads();
        const uint32_t st = sb + (uint32_t)(kt % 3) * 24576u;
#pragma unroll
        for (int kk = 0; kk < 2; kk++) {
            uint32_t aH[2][4], aL[2][4];
            const int arow = 32 * wm + (lane & 15);
            const int ach  = 2 * kk + (lane >> 4);
#pragma unroll
            for (int mi = 0; mi < 2; mi++) {
                uint32_t off = swzA(arow + 16 * mi, ach);
                ldm_x4(aH[mi], st + off);
                ldm_x4(aL[mi], st + 8192u + off);
            }
            const int brow = 16 * kk + (lane & 7) + ((lane >> 3) & 1) * 8;
#pragma unroll
            for (int nn = 0; nn < 4; nn++) {
                const int bch = 8 * wn + 2 * nn + (lane >> 4);
                uint32_t bh[4];
                ldm_x4_t(bh, st + 16384u + swzB(brow, bch));
#pragma unroll
                for (int sub = 0; sub < 2; sub++) {
                    const int ni = 2 * nn + sub;
#pragma unroll
                    for (int mi = 0; mi < 2; mi++) {
                        mma16816(acc[mi][ni], aH[mi], bh + 2 * sub);
                        mma16816(acc[mi][ni], aL[mi], bh + 2 * sub);
                    }
                }
            }
        }
        if (kt + 2 < KT) issue(kt + 2);
        else cp_commit();    // empty group keeps wait arithmetic valid
    }

#pragma unroll
    for (int mi = 0; mi < 2; mi++) {
        int rA = row0 + 32 * wm + 16 * mi + g;
#pragma unroll
        for (int ni = 0; ni < 8; ni++) {
            int col = col0 + 64 * wn + 8 * ni + 2 * t4;
            if (MODE == 0) {
                float2 v0 = {acc[mi][ni][0], acc[mi][ni][1]};
                float2 v1 = {acc[mi][ni][2], acc[mi][ni][3]};
                *reinterpret_cast<float2*>(C + (size_t)rA * N + col) = v0;
                *reinterpret_cast<float2*>(C + (size_t)(rA + 8) * N + col) = v1;
            } else {
                if (col0 < INNER_) {
                    uint32_t h, l;
                    split2h(acc[mi][ni][0], acc[mi][ni][1], h, l);
                    *reinterpret_cast<uint32_t*>(Qh + (size_t)rA * INNER_ + col) = h;
                    *reinterpret_cast<uint32_t*>(Ql + (size_t)rA * INNER_ + col) = l;
                    split2h(acc[mi][ni][2], acc[mi][ni][3], h, l);
                    *reinterpret_cast<uint32_t*>(Qh + (size_t)(rA + 8) * INNER_ + col) = h;
                    *reinterpret_cast<uint32_t*>(Ql + (size_t)(rA + 8) * INNER_ + col) = l;
                } else {
                    int ck = col - INNER_;
                    *reinterpret_cast<uint32_t*>(KV + (size_t)rA * (2 * INNER_) + ck) =
                        pack2h(acc[mi][ni][0], acc[mi][ni][1]);
                    *reinterpret_cast<uint32_t*>(KV + (size_t)(rA + 8) * (2 * INNER_) + ck) =
                        pack2h(acc[mi][ni][2], acc[mi][ni][3]);
                }
            }
        }
    }
}

// ---------------------------------------------------------------------------
// Flash attention, split-KV across warp pair (wn): each wn warp runs an
// independent online softmax over its 64-key half-stream (own m/l/O in
// registers, zero per-iter smem stats, ONE sync per iter), merged exactly
// once at the end: O = (O0*e^(m0-M) + O1*e^(m1-M)) / (l0*e^(m0-M)+l1*e^(m1-M)).
// 3-stage KV pipeline. Smem: Qh 0 | Ql 16K | stage(kt%3) at 32K+32K*s {K|V}
// | merge arrays at 128K. Total 132096.
// ---------------------------------------------------------------------------
namespace { constexpr int FLASH_SMEM = 131072 + 1024; }

__global__ void __launch_bounds__(256)
flash_kernel(const __half* __restrict__ qh, const __half* __restrict__ ql,
             const __half* __restrict__ kv,
             __half* __restrict__ atth, __half* __restrict__ attl) {
    extern __shared__ char sm_[];
    const uint32_t sb = smem_u32(sm_);
    float* sM2 = (float*)(sm_ + 131072);        // [128] wn=1 row max
    float* sL2 = sM2 + 128;                     // [128] wn=1 row sum

    const int tid = threadIdx.x, lane = tid & 31, w = tid >> 5;
    const int wm = w >> 1, wn = w & 1, g = lane >> 2, t4 = lane & 3;
    const int qt = blockIdx.x, h = blockIdx.y, b = blockIdx.z;
    const size_t qrow0 = (size_t)(b * N_ + qt * 128);

    // stage Q hi/lo (rides stage-0's commit group)
    {
        int r = tid >> 3, c = tid & 7;
        const __half* ph = qh + (qrow0 + r) * INNER_ + h * 64 + c * 8;
        const __half* pl = ql + (qrow0 + r) * INNER_ + h * 64 + c * 8;
#pragma unroll
        for (int it = 0; it < 4; it++) {
            uint32_t o = swzF(r + 32 * it, c);
            size_t go = (size_t)(32 * it) * INNER_;
            cp16(sb + o, ph + go);
            cp16(sb + 16384u + o, pl + go);
        }
    }

    auto issueKV = [&](int kt) {
        const uint32_t st = sb + 32768u + (uint32_t)(kt % 3) * 32768u;
        int r = tid >> 3, c = tid & 7;
        size_t rowb = (size_t)(b * N_ + kt * 128);
        const __half* pk = kv + (rowb + r) * (2 * INNER_) + h * 64 + c * 8;
#pragma unroll
        for (int it = 0; it < 4; it++) {
            uint32_t o = swzF(r + 32 * it, c);
            size_t go = (size_t)(32 * it) * (2 * INNER_);
            cp16(st + o,           pk + go);
            cp16(st + 16384u + o,  pk + go + 512);
        }
        cp_commit();
    };

    issueKV(0);
    issueKV(1);

    float o[2][8][4];
    float m[2][2], l[2][2];   // [mi][rowA/rowB], per-warp split-KV state
#pragma unroll
    for (int mi = 0; mi < 2; mi++) {
        m[mi][0] = -1e30f; m[mi][1] = -1e30f;
        l[mi][0] = 0.f;    l[mi][1] = 0.f;
#pragma unroll
        for (int ni = 0; ni < 8; ni++)
#pragma unroll
            for (int j = 0; j < 4; j++) o[mi][ni][j] = 0.f;
    }

    for (int kt = 0; kt < 16; kt++) {
        cp_wait1();
        __syncthreads();
        const uint32_t st = sb + 32768u + (uint32_t)(kt % 3) * 32768u;

        // ---- S = Q K^T over this warp's 64-key half ----
        float s[2][8][4];
#pragma unroll
        for (int mi = 0; mi < 2; mi++)
#pragma unroll
            for (int ni = 0; ni < 8; ni++)
#pragma unroll
                for (int j = 0; j < 4; j++) s[mi][ni][j] = 0.f;

#pragma unroll
        for (int kk = 0; kk < 4; kk++) {
            uint32_t aH[2][4], aL[2][4];
            const int arow = 32 * wm + (lane & 15);
            const int ach  = 2 * kk + (lane >> 4);
#pragma unroll
            for (int mi = 0; mi < 2; mi++) {
                uint32_t off = swzF(arow + 16 * mi, ach);
                ldm_x4(aH[mi], sb + off);
                ldm_x4(aL[mi], sb + 16384u + off);
            }
            const int krw = (lane & 7) + (lane >> 4) * 8;
            const int kch = 2 * kk + ((lane >> 3) & 1);
#pragma unroll
            for (int nn = 0; nn < 4; nn++) {
                uint32_t bh[4];
                ldm_x4(bh, st + swzF(64 * wn + 16 * nn + krw, kch));
#pragma unroll
                for (int sub = 0; sub < 2; sub++) {
                    const int ni = 2 * nn + sub;
#pragma unroll
                    for (int mi = 0; mi < 2; mi++) {
                        mma16816(s[mi][ni], aH[mi], bh + 2 * sub);
                        mma16816(s[mi][ni], aL[mi], bh + 2 * sub);
                    }
                }
            }
        }

        // ---- warp-local online softmax (registers only) ----
#pragma unroll
        for (int mi = 0; mi < 2; mi++) {
            float ma = -1e30f, mb = -1e30f;
#pragma unroll
            for (int ni = 0; ni < 8; ni++) {
                ma = fmaxf(ma, fmaxf(s[mi][ni][0], s[mi][ni][1]));
                mb = fmaxf(mb, fmaxf(s[mi][ni][2], s[mi][ni][3]));
            }
            ma = fmaxf(ma, __shfl_xor_sync(0xffffffffu, ma, 1));
            ma = fmaxf(ma, __shfl_xor_sync(0xffffffffu, ma, 2));
            mb = fmaxf(mb, __shfl_xor_sync(0xffffffffu, mb, 1));
            mb = fmaxf(mb, __shfl_xor_sync(0xffffffffu, mb, 2));

            float nmA = fmaxf(m[mi][0], ma);
            float nmB = fmaxf(m[mi][1], mb);
            float aA = __expf(m[mi][0] - nmA);
            float aB = __expf(m[mi][1] - nmB);
            m[mi][0] = nmA; m[mi][1] = nmB;

            float suA = 0.f, suB = 0.f;
#pragma unroll
            for (int ni = 0; ni < 8; ni++) {
                s[mi][ni][0] = __expf(s[mi][ni][0] - nmA);
                s[mi][ni][1] = __expf(s[mi][ni][1] - nmA);
                s[mi][ni][2] = __expf(s[mi][ni][2] - nmB);
                s[mi][ni][3] = __expf(s[mi][ni][3] - nmB);
                suA += s[mi][ni][0] + s[mi][ni][1];
                suB += s[mi][ni][2] + s[mi][ni][3];
            }
            suA += __shfl_xor_sync(0xffffffffu, suA, 1);
            suA += __shfl_xor_sync(0xffffffffu, suA, 2);
            suB += __shfl_xor_sync(0xffffffffu, suB, 1);
            suB += __shfl_xor_sync(0xffffffffu, suB, 2);
            l[mi][0] = aA * l[mi][0] + suA;
            l[mi][1] = aB * l[mi][1] + suB;

            // rescale O
#pragma unroll
            for (int ni = 0; ni < 8; ni++) {
                o[mi][ni][0] *= aA; o[mi][ni][1] *= aA;
                o[mi][ni][2] *= aB; o[mi][ni][3] *= aB;
            }
        }

        // ---- O += P @ V over this warp's 64-key half ----
#pragma unroll
        for (int kk2 = 0; kk2 < 4; kk2++) {
            uint32_t aH[2][4], aL[2][4];
#pragma unroll
            for (int mi = 0; mi < 2; mi++) {
                split2h(s[mi][2 * kk2][0],     s[mi][2 * kk2][1],     aH[mi][0], aL[mi][0]);
                split2h(s[mi][2 * kk2][2],     s[mi][2 * kk2][3],     aH[mi][1], aL[mi][1]);
                split2h(s[mi][2 * kk2 + 1][0], s[mi][2 * kk2 + 1][1], aH[mi][2], aL[mi][2]);
                split2h(s[mi][2 * kk2 + 1][2], s[mi][2 * kk2 + 1][3], aH[mi][3], aL[mi][3]);
            }
            const int vrw = 64 * wn + 16 * kk2 + (lane & 7) + ((lane >> 3) & 1) * 8;
#pragma unroll
            for (int nn = 0; nn < 4; nn++) {
                const int vch = 2 * nn + (lane >> 4);
                uint32_t bh[4];
                ldm_x4_t(bh, st + 16384u + swzF(vrw, vch));
#pragma unroll
                for (int sub = 0; sub < 2; sub++) {
                    const int ni = 2 * nn + sub;
#pragma unroll
                    for (int mi = 0; mi < 2; mi++) {
                        mma16816(o[mi][ni], aH[mi], bh + 2 * sub);
                        mma16816(o[mi][ni], aL[mi], bh + 2 * sub);
                    }
                }
            }
        }

        if (kt + 2 < 16) issueKV(kt + 2);
        else cp_commit();
    }

    // ---- merge the two split-KV halves (once), normalize, store ----
    __syncthreads();                    // everyone done with Q region
    float* sO = (float*)(sm_);          // reuse Q region: 128 x 64 fp32
    if (wn == 1) {
#pragma unroll
        for (int mi = 0; mi < 2; mi++) {
            int rA = 32 * wm + 16 * mi + g;
            if (t4 == 0) {
                sM2[rA]     = m[mi][0]; sL2[rA]     = l[mi][0];
                sM2[rA + 8] = m[mi][1]; sL2[rA + 8] = l[mi][1];
            }
#pragma unroll
            for (int ni = 0; ni < 8; ni++) {
                int d = 8 * ni + 2 * t4;
                sO[rA * 64 + d]           = o[mi][ni][0];
                sO[rA * 64 + d + 1]       = o[mi][ni][1];
                sO[(rA + 8) * 64 + d]     = o[mi][ni][2];
                sO[(rA + 8) * 64 + d + 1] = o[mi][ni][3];
            }
        }
    }
    __syncthreads();
    if (wn == 0) {
#pragma unroll
        for (int mi = 0; mi < 2; mi++) {
            int rA = 32 * wm + 16 * mi + g;
            int rB = rA + 8;
            float m1A = sM2[rA], m1B = sM2[rB];
            float MA = fmaxf(m[mi][0], m1A), MB = fmaxf(m[mi][1], m1B);
            float e0A = __expf(m[mi][0] - MA), e1A = __expf(m1A - MA);
            float e0B = __expf(m[mi][1] - MB), e1B = __expf(m1B - MB);
            float iA = 1.f / (l[mi][0] * e0A + sL2[rA] * e1A);
            float iB = 1.f / (l[mi][1] * e0B + sL2[rB] * e1B);
#pragma unroll
            for (int ni = 0; ni < 8; ni++) {
                int d = 8 * ni + 2 * t4;
                float v0 = (o[mi][ni][0] * e0A + sO[rA * 64 + d]     * e1A) * iA;
                float v1 = (o[mi][ni][1] * e0A + sO[rA * 64 + d + 1] * e1A) * iA;
                float v2 = (o[mi][ni][2] * e0B + sO[rB * 64 + d]     * e1B) * iB;
                float v3 = (o[mi][ni][3] * e0B + sO[rB * 64 + d + 1] * e1B) * iB;
                uint32_t hh, ll;
                split2h(v0, v1, hh, ll);
                *reinterpret_cast<uint32_t*>(atth + (qrow0 + rA) * INNER_ + h * 64 + d) = hh;
                *reinterpret_cast<uint32_t*>(attl + (qrow0 + rA) * INNER_ + h * 64 + d) = ll;
                split2h(v2, v3, hh, ll);
                *reinterpret_cast<uint32_t*>(atth + (qrow0 + rB) * INNER_ + h * 64 + d) = hh;
                *reinterpret_cast<uint32_t*>(attl + (qrow0 + rB) * INNER_ + h * 64 + d) = ll;
            }
        }
    }
}

// ---------------------------------------------------------------------------
extern "C" void kernel_launch(void* const* d_in, const int* /*in_sizes*/,
                              int /*n_in*/, void* d_out, int /*out_size*/) {
    const float* x   = (const float*)d_in[0];
    const float* g   = (const float*)d_in[1];
    const float* wq  = (const float*)d_in[2];
    const float* wkv = (const float*)d_in[3];
    const float* wo  = (const float*)d_in[4];
    float* out = (float*)d_out;

    __half *xnh, *xnl, *qh, *ql, *kv, *atth, *attl, *wqkv, *wo16;
    cudaGetSymbolAddress((void**)&xnh,  g_xnh);
    cudaGetSymbolAddress((void**)&xnl,  g_xnl);
    cudaGetSymbolAddress((void**)&qh,   g_qh);
    cudaGetSymbolAddress((void**)&ql,   g_ql);
    cudaGetSymbolAddress((void**)&kv,   g_kv16);
    cudaGetSymbolAddress((void**)&atth, g_atth);
    cudaGetSymbolAddress((void**)&attl, g_attl);
    cudaGetSymbolAddress((void**)&wqkv, g_wqkv16);
    cudaGetSymbolAddress((void**)&wo16, g_wo16);

    cudaFuncSetAttribute(gemm_fp16<0>,
                         cudaFuncAttributeMaxDynamicSharedMemorySize, GEMM_SMEM);
    cudaFuncSetAttribute(gemm_fp16<1>,
                         cudaFuncAttributeMaxDynamicSharedMemorySize, GEMM_SMEM);
    cudaFuncSetAttribute(flash_kernel,
                         cudaFuncAttributeMaxDynamicSharedMemorySize, FLASH_SMEM);

    // LayerNorm (sequence-axis stats) -> fp16 hi/lo
    ln_partial_kernel<<<dim3(DIM_ / 256, NCHUNK_, B_), 256>>>(x);
    ln_stats_kernel<<<dim3(DIM_ / 256, 1, B_), 256>>>(g);
    ln_norm_kernel<<<(B_ * N_ * DIM_ / 4) / 256, 256>>>(x);

    // weight conversion (single fp16, q scale folded)
    conv_qkv16<<<(DIM_ * QKVN_ / 4) / 256, 256>>>(wq, wkv);
    conv_wo16<<<(INNER_ * DIM_ / 4) / 256, 256>>>(wo);

    // fused qkv projection: [4096 x 1536]
    gemm_fp16<1><<<dim3(QKVN_ / 128, (B_ * N_) / 128), 256, GEMM_SMEM>>>(
        xnh, xnl, wqkv, nullptr, qh, ql, kv, DIM_, QKVN_);

    // fused attention (split-KV flash)
    flash_kernel<<<dim3(N_ / 128, HEADS_, B_), 256, FLASH_SMEM>>>(
        qh, ql, kv, atth, attl);

    // output projection: [4096 x 1024]
    gemm_fp16<0><<<dim3(DIM_ / 128, (B_ * N_) / 128), 256, GEMM_SMEM>>>(
        atth, attl, wo16, out, nullptr, nullptr, nullptr, INNER_, DIM_);
}